// round 3
// baseline (speedup 1.0000x reference)
#include <cuda_runtime.h>
#include <math.h>

#define Bc 4
#define Sc 2048
#define Ec 768
#define Hc 12
#define Dc 64
#define E3 2304
#define NGLOB 204

// Scratch
__device__ float g_qkv[(size_t)Bc * Sc * E3];
__device__ float g_attn[(size_t)Bc * Sc * Ec];
__device__ int   g_gcol[Sc];

__device__ __forceinline__ unsigned f2tf(float x) {
    unsigned r;
    asm("cvt.rna.tf32.f32 %0, %1;" : "=r"(r) : "f"(x));
    return r;
}

__device__ __forceinline__ void mma_tf32(float* d, const unsigned* a, unsigned b0, unsigned b1) {
    asm volatile(
        "mma.sync.aligned.m16n8k8.row.col.f32.tf32.tf32.f32 "
        "{%0,%1,%2,%3}, {%4,%5,%6,%7}, {%8,%9}, {%0,%1,%2,%3};"
        : "+f"(d[0]), "+f"(d[1]), "+f"(d[2]), "+f"(d[3])
        : "r"(a[0]), "r"(a[1]), "r"(a[2]), "r"(a[3]), "r"(b0), "r"(b1));
}

// ---------------------------------------------------------------------------
__global__ void gcol_kernel() {
    int t = threadIdx.x;
    for (int j = t; j < Sc; j += blockDim.x) g_gcol[j] = 0;
    __syncthreads();
    const float step = (float)((double)(Sc - 1) / (double)(NGLOB - 1));
    for (int k = t; k < NGLOB; k += blockDim.x) {
        int pos;
        if (k == NGLOB - 1) pos = Sc - 1;
        else                pos = (int)(__fmul_rn((float)k, step));
        if (pos < 0) pos = 0;
        if (pos > Sc - 1) pos = Sc - 1;
        g_gcol[pos] = 1;
    }
}

// ---------------------------------------------------------------------------
// tf32 tensor-core GEMM with register-prefetch double buffering.
// C[M,N] = A[M,K]*W[K,N] + bias.  M%128==0, N%128==0, K%32==0.
// 256 threads = 8 warps (4x2), warp tile 32x64, BK=32.
// ---------------------------------------------------------------------------
__global__ __launch_bounds__(256) void gemm_tf32(
    const float* __restrict__ A, const float* __restrict__ W,
    const float* __restrict__ bias, float* __restrict__ C,
    int M, int N, int K)
{
    __shared__ unsigned As[128][36];   // [m][k]
    __shared__ unsigned Bs[32][136];   // [k][n]

    const int tid = threadIdx.x;
    const int lane = tid & 31;
    const int w = tid >> 5;
    const int g = lane >> 2, c = lane & 3;
    const int wm = (w & 3) * 32;
    const int wn = (w >> 2) * 64;
    const int bx = blockIdx.x, by = blockIdx.y;

    // load coords
    const int aRow = tid >> 3;             // 0..127 (over 2 slots of 128)
    const int aCol = (tid & 7) << 2;
    const int bRow = tid >> 5;             // 0..7 (over 4 slots of 8)
    const int bCol = (tid & 31) << 2;

    const float* Aptr = A + (size_t)(by * 128) * K;
    const float* Wptr = W + (size_t)bx * 128;

    float acc[2][8][4];
#pragma unroll
    for (int mt = 0; mt < 2; mt++)
#pragma unroll
        for (int nt = 0; nt < 8; nt++)
#pragma unroll
            for (int i = 0; i < 4; i++) acc[mt][nt][i] = 0.f;

    // prologue: prefetch tile 0
    float4 apf[4], bpf[4];
#pragma unroll
    for (int i = 0; i < 4; i++) {
        int idx = tid + i * 256;
        int row = idx >> 3, kc = (idx & 7) << 2;
        apf[i] = *(const float4*)(Aptr + (size_t)row * K + kc);
        int kr = idx >> 5, nc = (idx & 31) << 2;
        bpf[i] = *(const float4*)(Wptr + (size_t)kr * N + nc);
    }

    const int NKT = K >> 5;
    for (int kt = 0; kt < NKT; kt++) {
        // store prefetched tile (convert to tf32)
#pragma unroll
        for (int i = 0; i < 4; i++) {
            int idx = tid + i * 256;
            int row = idx >> 3, kc = (idx & 7) << 2;
            *(uint4*)&As[row][kc] =
                make_uint4(f2tf(apf[i].x), f2tf(apf[i].y), f2tf(apf[i].z), f2tf(apf[i].w));
            int kr = idx >> 5, nc = (idx & 31) << 2;
            *(uint4*)&Bs[kr][nc] =
                make_uint4(f2tf(bpf[i].x), f2tf(bpf[i].y), f2tf(bpf[i].z), f2tf(bpf[i].w));
        }
        __syncthreads();

        // prefetch next tile (overlaps with mma below)
        if (kt + 1 < NKT) {
            const int k0 = (kt + 1) << 5;
#pragma unroll
            for (int i = 0; i < 4; i++) {
                int idx = tid + i * 256;
                int row = idx >> 3, kc = (idx & 7) << 2;
                apf[i] = *(const float4*)(Aptr + (size_t)row * K + k0 + kc);
                int kr = idx >> 5, nc = (idx & 31) << 2;
                bpf[i] = *(const float4*)(Wptr + (size_t)(k0 + kr) * N + nc);
            }
        }

#pragma unroll
        for (int ks = 0; ks < 4; ks++) {
            const int kk = ks * 8;
            unsigned a[2][4];
#pragma unroll
            for (int mt = 0; mt < 2; mt++) {
                int m = wm + mt * 16 + g;
                a[mt][0] = As[m][kk + c];
                a[mt][1] = As[m + 8][kk + c];
                a[mt][2] = As[m][kk + c + 4];
                a[mt][3] = As[m + 8][kk + c + 4];
            }
#pragma unroll
            for (int nt = 0; nt < 8; nt++) {
                unsigned b0 = Bs[kk + c][wn + nt * 8 + g];
                unsigned b1 = Bs[kk + c + 4][wn + nt * 8 + g];
#pragma unroll
                for (int mt = 0; mt < 2; mt++)
                    mma_tf32(acc[mt][nt], a[mt], b0, b1);
            }
        }
        __syncthreads();
    }

    // epilogue
#pragma unroll
    for (int mt = 0; mt < 2; mt++) {
        int r0 = by * 128 + wm + mt * 16 + g;
#pragma unroll
        for (int nt = 0; nt < 8; nt++) {
            int col = bx * 128 + wn + nt * 8 + 2 * c;
            float bv0 = bias[col], bv1 = bias[col + 1];
            float2 o0 = make_float2(acc[mt][nt][0] + bv0, acc[mt][nt][1] + bv1);
            float2 o1 = make_float2(acc[mt][nt][2] + bv0, acc[mt][nt][3] + bv1);
            *(float2*)(C + (size_t)r0 * N + col) = o0;
            *(float2*)(C + (size_t)(r0 + 8) * N + col) = o1;
        }
    }
}

// ---------------------------------------------------------------------------
// Tensor-core attention: block = (qtile128, head, batch); 8 warps x 16 q-rows.
// Keys stored pi-permuted so QK accumulator layout == PV A-fragment layout.
// ---------------------------------------------------------------------------
__global__ __launch_bounds__(256) void attn_tc(
    const float* __restrict__ qkv, float* __restrict__ out, int half_w)
{
    __shared__ unsigned Ks[64][68];  // permuted slot
    __shared__ unsigned Vs[64][72];  // natural key
    __shared__ int Gs[64];

    const int h = blockIdx.y, b = blockIdx.z;
    const bool is_local = (h < 8);
    const int q0 = blockIdx.x << 7;          // 128 q rows per block
    const int tid = threadIdx.x;
    const int lane = tid & 31;
    const int w = tid >> 5;
    const int g = lane >> 2, c = lane & 3;

    const float* qb = qkv + (size_t)b * Sc * E3 + h * Dc;
    const float* kb = qb + Ec;
    const float* vb = qb + 2 * Ec;

    // Q fragments in registers (pre-scaled, rna->tf32)
    const int r0 = q0 + 16 * w + g;
    const int r1 = r0 + 8;
    const float* qrow0 = qb + (size_t)r0 * E3;
    const float* qrow1 = qrow0 + (size_t)8 * E3;
    unsigned qa[8][4];
#pragma unroll
    for (int ks = 0; ks < 8; ks++) {
        qa[ks][0] = f2tf(qrow0[ks * 8 + c] * 0.125f);
        qa[ks][1] = f2tf(qrow1[ks * 8 + c] * 0.125f);
        qa[ks][2] = f2tf(qrow0[ks * 8 + c + 4] * 0.125f);
        qa[ks][3] = f2tf(qrow1[ks * 8 + c + 4] * 0.125f);
    }

    float o[8][4];
#pragma unroll
    for (int nt = 0; nt < 8; nt++)
#pragma unroll
        for (int i = 0; i < 4; i++) o[nt][i] = 0.f;
    float m0 = -1e30f, m1 = -1e30f, l0 = 0.f, l1 = 0.f;

    int kt0, kt1;
    if (is_local) {
        int lo = (q0 - half_w) >> 6;
        kt0 = lo > 0 ? lo : 0;
        kt1 = (q0 + 127) >> 6;
    } else {
        kt0 = 0;
        kt1 = (Sc >> 6) - 1;
    }

    for (int kt = kt0; kt <= kt1; kt++) {
        const int k0 = kt << 6;
        __syncthreads();   // prior PV reads done before overwriting K/V

        if (tid < 64) Gs[tid] = g_gcol[k0 + tid];
#pragma unroll
        for (int i = 0; i < 4; i++) {
            int idx = tid + i * 256;
            int slot = idx >> 4, dc = (idx & 15) << 2;
            int jk = k0 + (slot & 56) + ((slot & 7) >> 1) + ((slot & 1) << 2);
            float4 kv = *(const float4*)(kb + (size_t)jk * E3 + dc);
            *(uint4*)&Ks[slot][dc] = make_uint4(f2tf(kv.x), f2tf(kv.y), f2tf(kv.z), f2tf(kv.w));
            float4 vv = *(const float4*)(vb + (size_t)(k0 + slot) * E3 + dc);
            *(uint4*)&Vs[slot][dc] = make_uint4(f2tf(vv.x), f2tf(vv.y), f2tf(vv.z), f2tf(vv.w));
        }
        __syncthreads();

        // QK^T
        float s[8][4];
#pragma unroll
        for (int nt = 0; nt < 8; nt++)
#pragma unroll
            for (int i = 0; i < 4; i++) s[nt][i] = 0.f;
#pragma unroll
        for (int ks = 0; ks < 8; ks++) {
            const int kk = ks * 8;
#pragma unroll
            for (int nt = 0; nt < 8; nt++) {
                unsigned b0 = Ks[nt * 8 + g][kk + c];
                unsigned b1 = Ks[nt * 8 + g][kk + c + 4];
                mma_tf32(s[nt], qa[ks], b0, b1);
            }
        }

        // mask
#pragma unroll
        for (int nt = 0; nt < 8; nt++) {
            int jA = k0 + 8 * nt + c;
            int jB = jA + 4;
            bool okA0, okB0, okA1, okB1;
            if (is_local) {
                okA0 = (jA <= r0) && (jA >= r0 - half_w);
                okB0 = (jB <= r0) && (jB >= r0 - half_w);
                okA1 = (jA <= r1) && (jA >= r1 - half_w);
                okB1 = (jB <= r1) && (jB >= r1 - half_w);
            } else {
                int gA = Gs[8 * nt + c], gB = Gs[8 * nt + c + 4];
                okA0 = (jA <= r0) || gA;
                okB0 = (jB <= r0) || gB;
                okA1 = (jA <= r1) || gA;
                okB1 = (jB <= r1) || gB;
            }
            s[nt][0] = okA0 ? s[nt][0] : -1e9f;
            s[nt][1] = okB0 ? s[nt][1] : -1e9f;
            s[nt][2] = okA1 ? s[nt][2] : -1e9f;
            s[nt][3] = okB1 ? s[nt][3] : -1e9f;
        }

        // online softmax (rows r0: regs 0,1 ; r1: regs 2,3)
        float mx0 = -1e30f, mx1 = -1e30f;
#pragma unroll
        for (int nt = 0; nt < 8; nt++) {
            mx0 = fmaxf(mx0, fmaxf(s[nt][0], s[nt][1]));
            mx1 = fmaxf(mx1, fmaxf(s[nt][2], s[nt][3]));
        }
        mx0 = fmaxf(mx0, __shfl_xor_sync(0xffffffffu, mx0, 1));
        mx0 = fmaxf(mx0, __shfl_xor_sync(0xffffffffu, mx0, 2));
        mx1 = fmaxf(mx1, __shfl_xor_sync(0xffffffffu, mx1, 1));
        mx1 = fmaxf(mx1, __shfl_xor_sync(0xffffffffu, mx1, 2));

        float mn0 = fmaxf(m0, mx0), mn1 = fmaxf(m1, mx1);
        float f0 = __expf(m0 - mn0), f1 = __expf(m1 - mn1);
        m0 = mn0; m1 = mn1;

        float ps0 = 0.f, ps1 = 0.f;
#pragma unroll
        for (int nt = 0; nt < 8; nt++) {
            s[nt][0] = __expf(s[nt][0] - mn0);
            s[nt][1] = __expf(s[nt][1] - mn0);
            s[nt][2] = __expf(s[nt][2] - mn1);
            s[nt][3] = __expf(s[nt][3] - mn1);
            ps0 += s[nt][0] + s[nt][1];
            ps1 += s[nt][2] + s[nt][3];
            o[nt][0] *= f0; o[nt][1] *= f0;
            o[nt][2] *= f1; o[nt][3] *= f1;
        }
        ps0 += __shfl_xor_sync(0xffffffffu, ps0, 1);
        ps0 += __shfl_xor_sync(0xffffffffu, ps0, 2);
        ps1 += __shfl_xor_sync(0xffffffffu, ps1, 1);
        ps1 += __shfl_xor_sync(0xffffffffu, ps1, 2);
        l0 = l0 * f0 + ps0;
        l1 = l1 * f1 + ps1;

        // PV (interleave trick: score regs ARE the A-fragments)
#pragma unroll
        for (int ktile = 0; ktile < 8; ktile++) {
            unsigned pa[4];
            pa[0] = f2tf(s[ktile][0]);
            pa[1] = f2tf(s[ktile][2]);
            pa[2] = f2tf(s[ktile][1]);
            pa[3] = f2tf(s[ktile][3]);
#pragma unroll
            for (int nt = 0; nt < 8; nt++) {
                unsigned b0 = Vs[8 * ktile + c][8 * nt + g];
                unsigned b1 = Vs[8 * ktile + c + 4][8 * nt + g];
                mma_tf32(o[nt], pa, b0, b1);
            }
        }
    }

    // write [B,S,H*D]
    float inv0 = 1.0f / l0, inv1 = 1.0f / l1;
    float* ob0 = out + (size_t)(b * Sc + r0) * Ec + h * Dc;
    float* ob1 = out + (size_t)(b * Sc + r1) * Ec + h * Dc;
#pragma unroll
    for (int nt = 0; nt < 8; nt++) {
        int d = 8 * nt + 2 * c;
        *(float2*)(ob0 + d) = make_float2(o[nt][0] * inv0, o[nt][1] * inv0);
        *(float2*)(ob1 + d) = make_float2(o[nt][2] * inv1, o[nt][3] * inv1);
    }
}

// ---------------------------------------------------------------------------
extern "C" void kernel_launch(void* const* d_in, const int* in_sizes, int n_in,
                              void* d_out, int out_size) {
    const float* x      = (const float*)d_in[0];
    const float* w_attn = (const float*)d_in[1];
    const float* b_attn = (const float*)d_in[2];
    const float* w_proj = (const float*)d_in[3];
    const float* b_proj = (const float*)d_in[4];
    float* out = (float*)d_out;

    float *qkv_p = nullptr, *attn_p = nullptr;
    cudaGetSymbolAddress((void**)&qkv_p, g_qkv);
    cudaGetSymbolAddress((void**)&attn_p, g_attn);

    int wdw = (int)(128.0 * sqrt((double)Sc / 128.0));
    if (wdw < 32) wdw = 32;
    if (wdw > 512) wdw = 512;
    int half_w = wdw / 2;

    gcol_kernel<<<1, 256>>>();

    dim3 g1(E3 / 128, (Bc * Sc) / 128);
    gemm_tf32<<<g1, 256>>>(x, w_attn, b_attn, qkv_p, Bc * Sc, E3, Ec);

    dim3 ga(Sc / 128, Hc, Bc);
    attn_tc<<<ga, 256>>>(qkv_p, attn_p, half_w);

    dim3 g2(Ec / 128, (Bc * Sc) / 128);
    gemm_tf32<<<g2, 256>>>(attn_p, w_proj, b_proj, out, Bc * Sc, Ec, Ec);
}

// round 5
// speedup vs baseline: 1.1084x; 1.1084x over previous
#include <cuda_runtime.h>
#include <math.h>
#include <stdint.h>

#define Bc 4
#define Sc 2048
#define Ec 768
#define Hc 12
#define Dc 64
#define E3 2304
#define NGLOB 204

// Scratch (device globals; no runtime allocation allowed)
__device__ float g_qkv[(size_t)Bc * Sc * E3];     // [B,S,3E]
__device__ float g_attn[(size_t)Bc * Sc * Ec];    // [B,S,H*D] (tf32-rounded)
__device__ float g_xr[(size_t)Bc * Sc * Ec];      // x, tf32-rounded
__device__ float g_war[(size_t)Ec * E3];          // w_attn rounded (same layout)
__device__ float g_wpr[(size_t)Ec * Ec];          // w_proj rounded
__device__ int   g_gcol[Sc];

// ---------------------------------------------------------------------------
__device__ __forceinline__ unsigned f2tf(float x) {
    unsigned r;
    asm("cvt.rna.tf32.f32 %0, %1;" : "=r"(r) : "f"(x));
    return r;
}
__device__ __forceinline__ float roundtf(float x) { return __uint_as_float(f2tf(x)); }

__device__ __forceinline__ void mma_tf32(float* d, const unsigned* a, unsigned b0, unsigned b1) {
    asm volatile(
        "mma.sync.aligned.m16n8k8.row.col.f32.tf32.tf32.f32 "
        "{%0,%1,%2,%3}, {%4,%5,%6,%7}, {%8,%9}, {%0,%1,%2,%3};"
        : "+f"(d[0]), "+f"(d[1]), "+f"(d[2]), "+f"(d[3])
        : "r"(a[0]), "r"(a[1]), "r"(a[2]), "r"(a[3]), "r"(b0), "r"(b1));
}
__device__ __forceinline__ uint32_t smem_u32(const void* p) {
    uint32_t a;
    asm("{ .reg .u64 t; cvta.to.shared.u64 t, %1; cvt.u32.u64 %0, t; }" : "=r"(a) : "l"(p));
    return a;
}
__device__ __forceinline__ void cpa16(uint32_t dst, const void* src) {
    asm volatile("cp.async.cg.shared.global [%0], [%1], 16;" :: "r"(dst), "l"(src));
}
__device__ __forceinline__ void cpa_commit() {
    asm volatile("cp.async.commit_group;" ::: "memory");
}

// ---------------------------------------------------------------------------
__global__ void gcol_kernel() {
    int t = threadIdx.x;
    for (int j = t; j < Sc; j += blockDim.x) g_gcol[j] = 0;
    __syncthreads();
    const float step = (float)((double)(Sc - 1) / (double)(NGLOB - 1));
    for (int k = t; k < NGLOB; k += blockDim.x) {
        int pos;
        if (k == NGLOB - 1) pos = Sc - 1;
        else                pos = (int)(__fmul_rn((float)k, step));
        if (pos < 0) pos = 0;
        if (pos > Sc - 1) pos = Sc - 1;
        g_gcol[pos] = 1;
    }
}

__global__ void round_kernel(const float* __restrict__ in, float* __restrict__ outp, int n4) {
    int i = blockIdx.x * blockDim.x + threadIdx.x;
    if (i < n4) {
        float4 v = ((const float4*)in)[i];
        ((float4*)outp)[i] = make_float4(roundtf(v.x), roundtf(v.y), roundtf(v.z), roundtf(v.w));
    }
}

// ---------------------------------------------------------------------------
// tf32 mma.sync GEMM with 3-stage cp.async pipeline.
// C[M,N] = A[M,K]*W[K,N] + bias. Inputs pre-rounded to tf32 (no cvt in loop).
// 256 threads = 8 warps (4x2), warp tile 32x64, BK=32.
// Stage layout (bytes): A[128][36w]=18432  B[32][136w]=17408  -> 35840/stage
// ---------------------------------------------------------------------------
#define ST_BYTES 35840
#define ST_BOFF  18432
#define GS_TOTAL (3 * ST_BYTES)

__device__ __forceinline__ void copy_stage(const float* __restrict__ A, const float* __restrict__ W,
                                           int m0, int n0, int K, int N, int kt,
                                           uint32_t sbase, int tid) {
    const int kb = kt * 32;
    const uint32_t sA = sbase, sB = sbase + ST_BOFF;
#pragma unroll
    for (int i = 0; i < 4; i++) {
        int idx = tid + i * 256;
        int row = idx >> 3, c = idx & 7;
        cpa16(sA + row * 144 + c * 16, A + (size_t)(m0 + row) * K + kb + c * 4);
    }
#pragma unroll
    for (int i = 0; i < 4; i++) {
        int idx = tid + i * 256;
        int kr = idx >> 5, nc = idx & 31;
        cpa16(sB + kr * 544 + nc * 16, W + (size_t)(kb + kr) * N + n0 + nc * 4);
    }
    cpa_commit();
}

__global__ __launch_bounds__(256, 2) void gemm_tf32(
    const float* __restrict__ A, const float* __restrict__ W,
    const float* __restrict__ bias, float* __restrict__ C,
    int M, int N, int K)
{
    extern __shared__ char smem[];
    const uint32_t sb = smem_u32(smem);

    const int tid = threadIdx.x;
    const int lane = tid & 31;
    const int w = tid >> 5;
    const int g = lane >> 2, c = lane & 3;
    const int wm = (w & 3) * 32;
    const int wn = (w >> 2) * 64;
    const int bx = blockIdx.x, by = blockIdx.y;
    const int m0 = by << 7, n0 = bx << 7;
    const int NT = K >> 5;

    float acc[2][8][4];
#pragma unroll
    for (int mt = 0; mt < 2; mt++)
#pragma unroll
        for (int nt = 0; nt < 8; nt++)
#pragma unroll
            for (int i = 0; i < 4; i++) acc[mt][nt][i] = 0.f;

    // prologue: 3 stages in flight
    copy_stage(A, W, m0, n0, K, N, 0, sb, tid);
    copy_stage(A, W, m0, n0, K, N, 1, sb + ST_BYTES, tid);
    copy_stage(A, W, m0, n0, K, N, 2, sb + 2 * ST_BYTES, tid);

    for (int kt = 0; kt < NT; kt++) {
        asm volatile("cp.async.wait_group 2;" ::: "memory");
        __syncthreads();

        const uint32_t st = sb + (kt % 3) * ST_BYTES;
        const unsigned* As = (const unsigned*)(smem + (kt % 3) * ST_BYTES);
        const unsigned* Bs = (const unsigned*)(smem + (kt % 3) * ST_BYTES + ST_BOFF);
        (void)st;

#pragma unroll
        for (int ks = 0; ks < 4; ks++) {
            const int kk = ks * 8;
            unsigned a[2][4];
#pragma unroll
            for (int mt = 0; mt < 2; mt++) {
                int m = wm + mt * 16 + g;
                a[mt][0] = As[m * 36 + kk + c];
                a[mt][1] = As[(m + 8) * 36 + kk + c];
                a[mt][2] = As[m * 36 + kk + c + 4];
                a[mt][3] = As[(m + 8) * 36 + kk + c + 4];
            }
#pragma unroll
            for (int nt = 0; nt < 8; nt++) {
                unsigned b0 = Bs[(kk + c) * 136 + wn + nt * 8 + g];
                unsigned b1 = Bs[(kk + c + 4) * 136 + wn + nt * 8 + g];
#pragma unroll
                for (int mt = 0; mt < 2; mt++)
                    mma_tf32(acc[mt][nt], a[mt], b0, b1);
            }
        }
        __syncthreads();

        if (kt + 3 < NT) copy_stage(A, W, m0, n0, K, N, kt + 3, sb + (kt % 3) * ST_BYTES, tid);
        else             cpa_commit();   // keep group count uniform
    }

    // epilogue
#pragma unroll
    for (int mt = 0; mt < 2; mt++) {
        int r0 = m0 + wm + mt * 16 + g;
#pragma unroll
        for (int nt = 0; nt < 8; nt++) {
            int col = n0 + wn + nt * 8 + 2 * c;
            float bv0 = bias[col], bv1 = bias[col + 1];
            float2 o0 = make_float2(acc[mt][nt][0] + bv0, acc[mt][nt][1] + bv1);
            float2 o1 = make_float2(acc[mt][nt][2] + bv0, acc[mt][nt][3] + bv1);
            *(float2*)(C + (size_t)r0 * N + col) = o0;
            *(float2*)(C + (size_t)(r0 + 8) * N + col) = o1;
        }
    }
}

// ---------------------------------------------------------------------------
// Tensor-core attention (proven R2 shape): block = (qtile64, head, batch).
// Keys pi-permuted so QK accumulator layout == PV A-fragment layout.
// Output tf32-rounded (feeds proj GEMM with no cvt there).
// ---------------------------------------------------------------------------
__global__ __launch_bounds__(128) void attn_tc(
    const float* __restrict__ qkv, float* __restrict__ out, int half_w)
{
    __shared__ unsigned Ks[64][68];
    __shared__ unsigned Vs[64][72];
    __shared__ int Gs[64];

    const int qt = blockIdx.x, h = blockIdx.y, b = blockIdx.z;
    const bool is_local = (h < 8);
    const int q0 = qt << 6;
    const int tid = threadIdx.x;
    const int lane = tid & 31;
    const int w = tid >> 5;
    const int g = lane >> 2, c = lane & 3;

    const float* qb = qkv + (size_t)b * Sc * E3 + h * Dc;
    const float* kb = qb + Ec;
    const float* vb = qb + 2 * Ec;

    const int r0 = q0 + 16 * w + g;
    const float* qrow0 = qb + (size_t)r0 * E3;
    const float* qrow1 = qrow0 + (size_t)8 * E3;
    unsigned qa[8][4];
#pragma unroll
    for (int ks = 0; ks < 8; ks++) {
        qa[ks][0] = f2tf(qrow0[ks * 8 + c] * 0.125f);
        qa[ks][1] = f2tf(qrow1[ks * 8 + c] * 0.125f);
        qa[ks][2] = f2tf(qrow0[ks * 8 + c + 4] * 0.125f);
        qa[ks][3] = f2tf(qrow1[ks * 8 + c + 4] * 0.125f);
    }

    float o[8][4];
#pragma unroll
    for (int nt = 0; nt < 8; nt++)
#pragma unroll
        for (int i = 0; i < 4; i++) o[nt][i] = 0.f;
    float m0 = -1e30f, m1 = -1e30f, l0 = 0.f, l1 = 0.f;

    int kt0, kt1;
    if (is_local) {
        int lo = (q0 - half_w) >> 6;
        kt0 = lo > 0 ? lo : 0;
        kt1 = qt;
    } else {
        kt0 = 0;
        kt1 = (Sc >> 6) - 1;
    }

    for (int kt = kt0; kt <= kt1; kt++) {
        const int k0 = kt << 6;
        __syncthreads();

        if (tid < 64) Gs[tid] = g_gcol[k0 + tid];
#pragma unroll
        for (int i = 0; i < 8; i++) {
            int idx = tid + i * 128;
            int slot = idx >> 4, dc = (idx & 15) << 2;
            int jk = k0 + (slot & 56) + ((slot & 7) >> 1) + ((slot & 1) << 2);
            float4 kv = *(const float4*)(kb + (size_t)jk * E3 + dc);
            *(uint4*)&Ks[slot][dc] = make_uint4(f2tf(kv.x), f2tf(kv.y), f2tf(kv.z), f2tf(kv.w));
            float4 vv = *(const float4*)(vb + (size_t)(k0 + slot) * E3 + dc);
            *(uint4*)&Vs[slot][dc] = make_uint4(f2tf(vv.x), f2tf(vv.y), f2tf(vv.z), f2tf(vv.w));
        }
        __syncthreads();

        float s[8][4];
#pragma unroll
        for (int nt = 0; nt < 8; nt++)
#pragma unroll
            for (int i = 0; i < 4; i++) s[nt][i] = 0.f;
#pragma unroll
        for (int ks = 0; ks < 8; ks++) {
            const int kk = ks * 8;
#pragma unroll
            for (int nt = 0; nt < 8; nt++) {
                unsigned b0 = Ks[nt * 8 + g][kk + c];
                unsigned b1 = Ks[nt * 8 + g][kk + c + 4];
                mma_tf32(s[nt], qa[ks], b0, b1);
            }
        }

        const int r1 = r0 + 8;
#pragma unroll
        for (int nt = 0; nt < 8; nt++) {
            int jA = k0 + 8 * nt + c;
            int jB = jA + 4;
            bool okA0, okB0, okA1, okB1;
            if (is_local) {
                okA0 = (jA <= r0) && (jA >= r0 - half_w);
                okB0 = (jB <= r0) && (jB >= r0 - half_w);
                okA1 = (jA <= r1) && (jA >= r1 - half_w);
                okB1 = (jB <= r1) && (jB >= r1 - half_w);
            } else {
                int gA = Gs[8 * nt + c], gB = Gs[8 * nt + c + 4];
                okA0 = (jA <= r0) || gA;
                okB0 = (jB <= r0) || gB;
                okA1 = (jA <= r1) || gA;
                okB1 = (jB <= r1) || gB;
            }
            s[nt][0] = okA0 ? s[nt][0] : -1e9f;
            s[nt][1] = okB0 ? s[nt][1] : -1e9f;
            s[nt][2] = okA1 ? s[nt][2] : -1e9f;
            s[nt][3] = okB1 ? s[nt][3] : -1e9f;
        }

        float mx0 = -1e30f, mx1 = -1e30f;
#pragma unroll
        for (int nt = 0; nt < 8; nt++) {
            mx0 = fmaxf(mx0, fmaxf(s[nt][0], s[nt][1]));
            mx1 = fmaxf(mx1, fmaxf(s[nt][2], s[nt][3]));
        }
        mx0 = fmaxf(mx0, __shfl_xor_sync(0xffffffffu, mx0, 1));
        mx0 = fmaxf(mx0, __shfl_xor_sync(0xffffffffu, mx0, 2));
        mx1 = fmaxf(mx1, __shfl_xor_sync(0xffffffffu, mx1, 1));
        mx1 = fmaxf(mx1, __shfl_xor_sync(0xffffffffu, mx1, 2));

        float mn0 = fmaxf(m0, mx0), mn1 = fmaxf(m1, mx1);
        float f0 = __expf(m0 - mn0), f1 = __expf(m1 - mn1);
        m0 = mn0; m1 = mn1;

        float ps0 = 0.f, ps1 = 0.f;
#pragma unroll
        for (int nt = 0; nt < 8; nt++) {
            s[nt][0] = __expf(s[nt][0] - mn0);
            s[nt][1] = __expf(s[nt][1] - mn0);
            s[nt][2] = __expf(s[nt][2] - mn1);
            s[nt][3] = __expf(s[nt][3] - mn1);
            ps0 += s[nt][0] + s[nt][1];
            ps1 += s[nt][2] + s[nt][3];
            o[nt][0] *= f0; o[nt][1] *= f0;
            o[nt][2] *= f1; o[nt][3] *= f1;
        }
        ps0 += __shfl_xor_sync(0xffffffffu, ps0, 1);
        ps0 += __shfl_xor_sync(0xffffffffu, ps0, 2);
        ps1 += __shfl_xor_sync(0xffffffffu, ps1, 1);
        ps1 += __shfl_xor_sync(0xffffffffu, ps1, 2);
        l0 = l0 * f0 + ps0;
        l1 = l1 * f1 + ps1;

#pragma unroll
        for (int ktile = 0; ktile < 8; ktile++) {
            unsigned pa[4];
            pa[0] = f2tf(s[ktile][0]);
            pa[1] = f2tf(s[ktile][2]);
            pa[2] = f2tf(s[ktile][1]);
            pa[3] = f2tf(s[ktile][3]);
#pragma unroll
            for (int nt = 0; nt < 8; nt++) {
                unsigned b0 = Vs[8 * ktile + c][8 * nt + g];
                unsigned b1 = Vs[8 * ktile + c + 4][8 * nt + g];
                mma_tf32(o[nt], pa, b0, b1);
            }
        }
    }

    float inv0 = 1.0f / l0, inv1 = 1.0f / l1;
    float* ob0 = out + (size_t)(b * Sc + r0) * Ec + h * Dc;
    float* ob1 = out + (size_t)(b * Sc + r0 + 8) * Ec + h * Dc;
#pragma unroll
    for (int nt = 0; nt < 8; nt++) {
        int d = 8 * nt + 2 * c;
        *(float2*)(ob0 + d) = make_float2(roundtf(o[nt][0] * inv0), roundtf(o[nt][1] * inv0));
        *(float2*)(ob1 + d) = make_float2(roundtf(o[nt][2] * inv1), roundtf(o[nt][3] * inv1));
    }
}

// ---------------------------------------------------------------------------
extern "C" void kernel_launch(void* const* d_in, const int* in_sizes, int n_in,
                              void* d_out, int out_size) {
    const float* x      = (const float*)d_in[0];
    const float* w_attn = (const float*)d_in[1];
    const float* b_attn = (const float*)d_in[2];
    const float* w_proj = (const float*)d_in[3];
    const float* b_proj = (const float*)d_in[4];
    float* out = (float*)d_out;

    float *qkv_p, *attn_p, *xr_p, *war_p, *wpr_p;
    cudaGetSymbolAddress((void**)&qkv_p, g_qkv);
    cudaGetSymbolAddress((void**)&attn_p, g_attn);
    cudaGetSymbolAddress((void**)&xr_p, g_xr);
    cudaGetSymbolAddress((void**)&war_p, g_war);
    cudaGetSymbolAddress((void**)&wpr_p, g_wpr);

    int wdw = (int)(128.0 * sqrt((double)Sc / 128.0));
    if (wdw < 32) wdw = 32;
    if (wdw > 512) wdw = 512;
    int half_w = wdw / 2;

    cudaFuncSetAttribute(gemm_tf32, cudaFuncAttributeMaxDynamicSharedMemorySize, GS_TOTAL);

    gcol_kernel<<<1, 256>>>();
    {
        int n4 = (Bc * Sc * Ec) / 4;
        round_kernel<<<(n4 + 255) / 256, 256>>>(x, xr_p, n4);
    }
    {
        int n4 = (Ec * E3) / 4;
        round_kernel<<<(n4 + 255) / 256, 256>>>(w_attn, war_p, n4);
    }
    {
        int n4 = (Ec * Ec) / 4;
        round_kernel<<<(n4 + 255) / 256, 256>>>(w_proj, wpr_p, n4);
    }

    dim3 g1(E3 / 128, (Bc * Sc) / 128);
    gemm_tf32<<<g1, 256, GS_TOTAL>>>(xr_p, war_p, b_attn, qkv_p, Bc * Sc, E3, Ec);

    dim3 ga(Sc / 64, Hc, Bc);
    attn_tc<<<ga, 128>>>(qkv_p, attn_p, half_w);

    dim3 g2(Ec / 128, (Bc * Sc) / 128);
    gemm_tf32<<<g2, 256, GS_TOTAL>>>(attn_p, wpr_p, b_proj, out, Bc * Sc, Ec, Ec);
}

// round 6
// speedup vs baseline: 1.2740x; 1.1493x over previous
#include <cuda_runtime.h>
#include <math.h>
#include <stdint.h>

#define Bc 4
#define Sc 2048
#define Ec 768
#define Hc 12
#define Dc 64
#define E3 2304
#define NGLOB 204

// Scratch (device globals; no runtime allocation allowed)
__device__ float g_qkv[(size_t)Bc * Sc * E3];     // [B,S,3E] tf32-rounded
__device__ float g_attn[(size_t)Bc * Sc * Ec];    // [B,S,H*D] tf32-rounded
__device__ float g_xr[(size_t)Bc * Sc * Ec];      // x rounded
__device__ float g_war[(size_t)Ec * E3];          // w_attn rounded
__device__ float g_wpr[(size_t)Ec * Ec];          // w_proj rounded
__device__ float g_Kg[16 * 256 * 64];             // gathered global K (permuted in 64-blocks)
__device__ float g_Vg[16 * 256 * 64];             // gathered global V (natural)
__device__ int   g_gjpad[256];                    // global col indices, -1 pad
__device__ int   g_gstart[32];                    // per qtile: #gpos <= q0

// ---------------------------------------------------------------------------
__device__ __forceinline__ unsigned f2tf(float x) {
    unsigned r;
    asm("cvt.rna.tf32.f32 %0, %1;" : "=r"(r) : "f"(x));
    return r;
}
__device__ __forceinline__ float roundtf(float x) { return __uint_as_float(f2tf(x)); }

__device__ __forceinline__ void mma_tf32(float* d, const unsigned* a, unsigned b0, unsigned b1) {
    asm volatile(
        "mma.sync.aligned.m16n8k8.row.col.f32.tf32.tf32.f32 "
        "{%0,%1,%2,%3}, {%4,%5,%6,%7}, {%8,%9}, {%0,%1,%2,%3};"
        : "+f"(d[0]), "+f"(d[1]), "+f"(d[2]), "+f"(d[3])
        : "r"(a[0]), "r"(a[1]), "r"(a[2]), "r"(a[3]), "r"(b0), "r"(b1));
}
__device__ __forceinline__ uint32_t smem_u32(const void* p) {
    uint32_t a;
    asm("{ .reg .u64 t; cvta.to.shared.u64 t, %1; cvt.u32.u64 %0, t; }" : "=r"(a) : "l"(p));
    return a;
}
__device__ __forceinline__ void cpa16(uint32_t dst, const void* src) {
    asm volatile("cp.async.cg.shared.global [%0], [%1], 16;" :: "r"(dst), "l"(src));
}
__device__ __forceinline__ void cpa_commit() {
    asm volatile("cp.async.commit_group;" ::: "memory");
}

// ---------------------------------------------------------------------------
// global-column positions (linspace emulation), pad list, per-qtile start counts
// ---------------------------------------------------------------------------
__global__ void gpos_kernel() {
    int t = threadIdx.x;   // 256
    const float step = (float)((double)(Sc - 1) / (double)(NGLOB - 1));
    int j = -1;
    if (t < NGLOB) {
        if (t == NGLOB - 1) j = Sc - 1;
        else                j = (int)(__fmul_rn((float)t, step));
        if (j < 0) j = 0;
        if (j > Sc - 1) j = Sc - 1;
    }
    g_gjpad[t] = j;
    __syncthreads();
    if (t < 32) {
        int q0 = t * 64, cnt = 0;
        for (int k = 0; k < NGLOB; k++) cnt += (g_gjpad[k] <= q0) ? 1 : 0;
        g_gstart[t] = cnt;
    }
}

__global__ void round_kernel(const float* __restrict__ in, float* __restrict__ outp, int n4) {
    int i = blockIdx.x * blockDim.x + threadIdx.x;
    if (i < n4) {
        float4 v = ((const float4*)in)[i];
        ((float4*)outp)[i] = make_float4(roundtf(v.x), roundtf(v.y), roundtf(v.z), roundtf(v.w));
    }
}

// gather global-column K/V for heads 8..11 (K stored with 64-block pi-permutation)
__global__ __launch_bounds__(256) void gather_kernel(const float* __restrict__ qkv) {
    int blk = blockIdx.x;            // b*4 + (h-8)
    int b = blk >> 2, h = 8 + (blk & 3);
    const float* kb = qkv + (size_t)b * Sc * E3 + Ec + h * Dc;
    const float* vb = kb + Ec;
    float* Kg = g_Kg + (size_t)blk * 256 * 64;
    float* Vg = g_Vg + (size_t)blk * 256 * 64;
    int slot = threadIdx.x;
    int slo = slot & 63, t = slot >> 6;
    int pk = (slo & 56) + ((slo & 7) >> 1) + ((slo & 1) << 2);
    int jK = g_gjpad[t * 64 + pk];
    int jV = g_gjpad[slot];
    float4 z = make_float4(0.f, 0.f, 0.f, 0.f);
#pragma unroll
    for (int c16 = 0; c16 < 16; c16++) {
        float4 kv = (jK >= 0) ? *(const float4*)(kb + (size_t)jK * E3 + c16 * 4) : z;
        ((float4*)(Kg + (size_t)slot * 64))[c16] = kv;
        float4 vv = (jV >= 0) ? *(const float4*)(vb + (size_t)jV * E3 + c16 * 4) : z;
        ((float4*)(Vg + (size_t)slot * 64))[c16] = vv;
    }
}

// ---------------------------------------------------------------------------
// tf32 mma.sync GEMM with 3-stage cp.async pipeline (R5, + optional rounded out)
// ---------------------------------------------------------------------------
#define ST_BYTES 35840
#define ST_BOFF  18432
#define GS_TOTAL (3 * ST_BYTES)

__device__ __forceinline__ void copy_stage(const float* __restrict__ A, const float* __restrict__ W,
                                           int m0, int n0, int K, int N, int kt,
                                           uint32_t sbase, int tid) {
    const int kb = kt * 32;
    const uint32_t sA = sbase, sB = sbase + ST_BOFF;
#pragma unroll
    for (int i = 0; i < 4; i++) {
        int idx = tid + i * 256;
        int row = idx >> 3, c = idx & 7;
        cpa16(sA + row * 144 + c * 16, A + (size_t)(m0 + row) * K + kb + c * 4);
    }
#pragma unroll
    for (int i = 0; i < 4; i++) {
        int idx = tid + i * 256;
        int kr = idx >> 5, nc = idx & 31;
        cpa16(sB + kr * 544 + nc * 16, W + (size_t)(kb + kr) * N + n0 + nc * 4);
    }
    cpa_commit();
}

__global__ __launch_bounds__(256, 2) void gemm_tf32(
    const float* __restrict__ A, const float* __restrict__ W,
    const float* __restrict__ bias, float* __restrict__ C,
    int M, int N, int K, int roundOut)
{
    extern __shared__ char smem[];
    const uint32_t sb = smem_u32(smem);

    const int tid = threadIdx.x;
    const int lane = tid & 31;
    const int w = tid >> 5;
    const int g = lane >> 2, c = lane & 3;
    const int wm = (w & 3) * 32;
    const int wn = (w >> 2) * 64;
    const int m0 = blockIdx.y << 7, n0 = blockIdx.x << 7;
    const int NT = K >> 5;

    float acc[2][8][4];
#pragma unroll
    for (int mt = 0; mt < 2; mt++)
#pragma unroll
        for (int nt = 0; nt < 8; nt++)
#pragma unroll
            for (int i = 0; i < 4; i++) acc[mt][nt][i] = 0.f;

    copy_stage(A, W, m0, n0, K, N, 0, sb, tid);
    copy_stage(A, W, m0, n0, K, N, 1, sb + ST_BYTES, tid);
    copy_stage(A, W, m0, n0, K, N, 2, sb + 2 * ST_BYTES, tid);

    for (int kt = 0; kt < NT; kt++) {
        asm volatile("cp.async.wait_group 2;" ::: "memory");
        __syncthreads();

        const unsigned* As = (const unsigned*)(smem + (kt % 3) * ST_BYTES);
        const unsigned* Bs = (const unsigned*)(smem + (kt % 3) * ST_BYTES + ST_BOFF);

#pragma unroll
        for (int ks = 0; ks < 4; ks++) {
            const int kk = ks * 8;
            unsigned a[2][4];
#pragma unroll
            for (int mt = 0; mt < 2; mt++) {
                int m = wm + mt * 16 + g;
                a[mt][0] = As[m * 36 + kk + c];
                a[mt][1] = As[(m + 8) * 36 + kk + c];
                a[mt][2] = As[m * 36 + kk + c + 4];
                a[mt][3] = As[(m + 8) * 36 + kk + c + 4];
            }
#pragma unroll
            for (int nt = 0; nt < 8; nt++) {
                unsigned b0 = Bs[(kk + c) * 136 + wn + nt * 8 + g];
                unsigned b1 = Bs[(kk + c + 4) * 136 + wn + nt * 8 + g];
#pragma unroll
                for (int mt = 0; mt < 2; mt++)
                    mma_tf32(acc[mt][nt], a[mt], b0, b1);
            }
        }
        __syncthreads();

        if (kt + 3 < NT) copy_stage(A, W, m0, n0, K, N, kt + 3, sb + (kt % 3) * ST_BYTES, tid);
        else             cpa_commit();
    }

#pragma unroll
    for (int mt = 0; mt < 2; mt++) {
        int r0 = m0 + wm + mt * 16 + g;
#pragma unroll
        for (int nt = 0; nt < 8; nt++) {
            int col = n0 + wn + nt * 8 + 2 * c;
            float bv0 = bias[col], bv1 = bias[col + 1];
            float v00 = acc[mt][nt][0] + bv0, v01 = acc[mt][nt][1] + bv1;
            float v10 = acc[mt][nt][2] + bv0, v11 = acc[mt][nt][3] + bv1;
            if (roundOut) {
                v00 = roundtf(v00); v01 = roundtf(v01);
                v10 = roundtf(v10); v11 = roundtf(v11);
            }
            *(float2*)(C + (size_t)r0 * N + col) = make_float2(v00, v01);
            *(float2*)(C + (size_t)(r0 + 8) * N + col) = make_float2(v10, v11);
        }
    }
}

// ---------------------------------------------------------------------------
// Attention: cp.async double-buffered, cvt-free loads (qkv pre-rounded).
// Local heads: window tiles. Global heads: causal tiles (mask j<=i) +
// compact gathered global tiles (mask j>i, disjoint union == (j<=i)|gcol).
// ---------------------------------------------------------------------------
#define AKW 68
#define AVW 72
#define AST_BYTES 35840      // K 64*272 + V 64*288
#define AST_VOFF  17408

__device__ __forceinline__ void attn_issue(
    int it, int n_causal, int n_tiles, int kt_base, int ct0,
    const float* __restrict__ kb, const float* __restrict__ vb,
    const float* __restrict__ KgB, const float* __restrict__ VgB,
    uint32_t sbase, int tid)
{
    if (it >= n_tiles) { cpa_commit(); return; }
    const uint32_t sK = sbase, sV = sbase + AST_VOFF;
    if (it < n_causal) {
        const int k0 = (kt_base + it) << 6;
#pragma unroll
        for (int i = 0; i < 8; i++) {
            int ch = tid + i * 128;
            int slot = ch >> 4, c16 = ch & 15;
            int jk = k0 + (slot & 56) + ((slot & 7) >> 1) + ((slot & 1) << 2);
            cpa16(sK + slot * 272 + c16 * 16, kb + (size_t)jk * E3 + c16 * 4);
            cpa16(sV + slot * 288 + c16 * 16, vb + (size_t)(k0 + slot) * E3 + c16 * 4);
        }
    } else {
        const int ct = ct0 + it - n_causal;
        const float* Kt = KgB + (size_t)ct * 64 * 64;
        const float* Vt = VgB + (size_t)ct * 64 * 64;
#pragma unroll
        for (int i = 0; i < 8; i++) {
            int ch = tid + i * 128;
            int slot = ch >> 4, c16 = ch & 15;
            cpa16(sK + slot * 272 + c16 * 16, Kt + (size_t)slot * 64 + c16 * 4);
            cpa16(sV + slot * 288 + c16 * 16, Vt + (size_t)slot * 64 + c16 * 4);
        }
    }
    cpa_commit();
}

__global__ __launch_bounds__(128) void attn_tc(
    const float* __restrict__ qkv, float* __restrict__ out, int half_w)
{
    extern __shared__ char smem[];
    const uint32_t sb = smem_u32(smem);
    const unsigned* smw = (const unsigned*)smem;

    const int qt = blockIdx.x, h = blockIdx.y, b = blockIdx.z;
    const bool is_local = (h < 8);
    const int q0 = qt << 6;
    const int tid = threadIdx.x;
    const int lane = tid & 31;
    const int w = tid >> 5;
    const int g = lane >> 2, c = lane & 3;

    const float* qb = qkv + (size_t)b * Sc * E3 + h * Dc;
    const float* kb = qb + Ec;
    const float* vb = qb + 2 * Ec;
    const float* KgB = g_Kg + (size_t)(b * 4 + (h - 8)) * 256 * 64;
    const float* VgB = g_Vg + (size_t)(b * 4 + (h - 8)) * 256 * 64;

    // Q fragments: rounded qkv * 0.125 (exact pow2 scale -> still tf32)
    const int r0 = q0 + 16 * w + g;
    const int r1 = r0 + 8;
    const float* qrow0 = qb + (size_t)r0 * E3;
    const float* qrow1 = qrow0 + (size_t)8 * E3;
    unsigned qa[8][4];
#pragma unroll
    for (int ks = 0; ks < 8; ks++) {
        qa[ks][0] = __float_as_uint(qrow0[ks * 8 + c] * 0.125f);
        qa[ks][1] = __float_as_uint(qrow1[ks * 8 + c] * 0.125f);
        qa[ks][2] = __float_as_uint(qrow0[ks * 8 + c + 4] * 0.125f);
        qa[ks][3] = __float_as_uint(qrow1[ks * 8 + c + 4] * 0.125f);
    }

    float o[8][4];
#pragma unroll
    for (int nt = 0; nt < 8; nt++)
#pragma unroll
        for (int i = 0; i < 4; i++) o[nt][i] = 0.f;
    float m0 = -1e30f, m1 = -1e30f, l0 = 0.f, l1 = 0.f;

    int kt_base, n_causal, n_tiles, ct0 = 0;
    if (is_local) {
        int lo = (q0 - half_w) >> 6;
        kt_base = lo > 0 ? lo : 0;
        n_causal = qt - kt_base + 1;
        n_tiles = n_causal;
    } else {
        kt_base = 0;
        n_causal = qt + 1;
        ct0 = g_gstart[qt] >> 6;
        n_tiles = n_causal + (4 - ct0);
    }

    attn_issue(0, n_causal, n_tiles, kt_base, ct0, kb, vb, KgB, VgB, sb, tid);
    attn_issue(1, n_causal, n_tiles, kt_base, ct0, kb, vb, KgB, VgB, sb + AST_BYTES, tid);

    for (int it = 0; it < n_tiles; it++) {
        asm volatile("cp.async.wait_group 1;" ::: "memory");
        __syncthreads();

        const unsigned* Ks = smw + (it & 1) * (AST_BYTES / 4);
        const unsigned* Vs = Ks + 64 * AKW;
        const bool compact = (!is_local) && (it >= n_causal);
        const int k0 = (kt_base + it) << 6;
        const int ctb = compact ? (ct0 + it - n_causal) * 64 : 0;

        // QK^T
        float s[8][4];
#pragma unroll
        for (int nt = 0; nt < 8; nt++)
#pragma unroll
            for (int i = 0; i < 4; i++) s[nt][i] = 0.f;
#pragma unroll
        for (int ks = 0; ks < 8; ks++) {
            const int kk = ks * 8;
#pragma unroll
            for (int nt = 0; nt < 8; nt++) {
                unsigned b0 = Ks[(nt * 8 + g) * AKW + kk + c];
                unsigned b1 = Ks[(nt * 8 + g) * AKW + kk + c + 4];
                mma_tf32(s[nt], qa[ks], b0, b1);
            }
        }

        // mask
        if (is_local) {
#pragma unroll
            for (int nt = 0; nt < 8; nt++) {
                int jA = k0 + 8 * nt + c, jB = jA + 4;
                s[nt][0] = (jA <= r0 && jA >= r0 - half_w) ? s[nt][0] : -1e9f;
                s[nt][1] = (jB <= r0 && jB >= r0 - half_w) ? s[nt][1] : -1e9f;
                s[nt][2] = (jA <= r1 && jA >= r1 - half_w) ? s[nt][2] : -1e9f;
                s[nt][3] = (jB <= r1 && jB >= r1 - half_w) ? s[nt][3] : -1e9f;
            }
        } else if (!compact) {
#pragma unroll
            for (int nt = 0; nt < 8; nt++) {
                int jA = k0 + 8 * nt + c, jB = jA + 4;
                s[nt][0] = (jA <= r0) ? s[nt][0] : -1e9f;
                s[nt][1] = (jB <= r0) ? s[nt][1] : -1e9f;
                s[nt][2] = (jA <= r1) ? s[nt][2] : -1e9f;
                s[nt][3] = (jB <= r1) ? s[nt][3] : -1e9f;
            }
        } else {
#pragma unroll
            for (int nt = 0; nt < 8; nt++) {
                int jA = g_gjpad[ctb + 8 * nt + c];
                int jB = g_gjpad[ctb + 8 * nt + c + 4];
                s[nt][0] = (jA > r0) ? s[nt][0] : -1e9f;
                s[nt][1] = (jB > r0) ? s[nt][1] : -1e9f;
                s[nt][2] = (jA > r1) ? s[nt][2] : -1e9f;
                s[nt][3] = (jB > r1) ? s[nt][3] : -1e9f;
            }
        }

        // online softmax
        float mx0 = -1e30f, mx1 = -1e30f;
#pragma unroll
        for (int nt = 0; nt < 8; nt++) {
            mx0 = fmaxf(mx0, fmaxf(s[nt][0], s[nt][1]));
            mx1 = fmaxf(mx1, fmaxf(s[nt][2], s[nt][3]));
        }
        mx0 = fmaxf(mx0, __shfl_xor_sync(0xffffffffu, mx0, 1));
        mx0 = fmaxf(mx0, __shfl_xor_sync(0xffffffffu, mx0, 2));
        mx1 = fmaxf(mx1, __shfl_xor_sync(0xffffffffu, mx1, 1));
        mx1 = fmaxf(mx1, __shfl_xor_sync(0xffffffffu, mx1, 2));

        float mn0 = fmaxf(m0, mx0), mn1 = fmaxf(m1, mx1);
        float f0 = __expf(m0 - mn0), f1 = __expf(m1 - mn1);
        m0 = mn0; m1 = mn1;

        float ps0 = 0.f, ps1 = 0.f;
#pragma unroll
        for (int nt = 0; nt < 8; nt++) {
            s[nt][0] = __expf(s[nt][0] - mn0);
            s[nt][1] = __expf(s[nt][1] - mn0);
            s[nt][2] = __expf(s[nt][2] - mn1);
            s[nt][3] = __expf(s[nt][3] - mn1);
            ps0 += s[nt][0] + s[nt][1];
            ps1 += s[nt][2] + s[nt][3];
            o[nt][0] *= f0; o[nt][1] *= f0;
            o[nt][2] *= f1; o[nt][3] *= f1;
        }
        ps0 += __shfl_xor_sync(0xffffffffu, ps0, 1);
        ps0 += __shfl_xor_sync(0xffffffffu, ps0, 2);
        ps1 += __shfl_xor_sync(0xffffffffu, ps1, 1);
        ps1 += __shfl_xor_sync(0xffffffffu, ps1, 2);
        l0 = l0 * f0 + ps0;
        l1 = l1 * f1 + ps1;

        // PV (interleave trick)
#pragma unroll
        for (int ktile = 0; ktile < 8; ktile++) {
            unsigned pa[4];
            pa[0] = f2tf(s[ktile][0]);
            pa[1] = f2tf(s[ktile][2]);
            pa[2] = f2tf(s[ktile][1]);
            pa[3] = f2tf(s[ktile][3]);
#pragma unroll
            for (int nt = 0; nt < 8; nt++) {
                unsigned b0 = Vs[(8 * ktile + c) * AVW + 8 * nt + g];
                unsigned b1 = Vs[(8 * ktile + c + 4) * AVW + 8 * nt + g];
                mma_tf32(o[nt], pa, b0, b1);
            }
        }
        __syncthreads();

        attn_issue(it + 2, n_causal, n_tiles, kt_base, ct0, kb, vb, KgB, VgB,
                   sb + (it & 1) * AST_BYTES, tid);
    }

    // write [B,S,H*D] tf32-rounded
    float inv0 = 1.0f / l0, inv1 = 1.0f / l1;
    float* ob0 = out + (size_t)(b * Sc + r0) * Ec + h * Dc;
    float* ob1 = out + (size_t)(b * Sc + r1) * Ec + h * Dc;
#pragma unroll
    for (int nt = 0; nt < 8; nt++) {
        int d = 8 * nt + 2 * c;
        *(float2*)(ob0 + d) = make_float2(roundtf(o[nt][0] * inv0), roundtf(o[nt][1] * inv0));
        *(float2*)(ob1 + d) = make_float2(roundtf(o[nt][2] * inv1), roundtf(o[nt][3] * inv1));
    }
}

// ---------------------------------------------------------------------------
extern "C" void kernel_launch(void* const* d_in, const int* in_sizes, int n_in,
                              void* d_out, int out_size) {
    const float* x      = (const float*)d_in[0];
    const float* w_attn = (const float*)d_in[1];
    const float* b_attn = (const float*)d_in[2];
    const float* w_proj = (const float*)d_in[3];
    const float* b_proj = (const float*)d_in[4];
    float* out = (float*)d_out;

    float *qkv_p, *attn_p, *xr_p, *war_p, *wpr_p;
    cudaGetSymbolAddress((void**)&qkv_p, g_qkv);
    cudaGetSymbolAddress((void**)&attn_p, g_attn);
    cudaGetSymbolAddress((void**)&xr_p, g_xr);
    cudaGetSymbolAddress((void**)&war_p, g_war);
    cudaGetSymbolAddress((void**)&wpr_p, g_wpr);

    int wdw = (int)(128.0 * sqrt((double)Sc / 128.0));
    if (wdw < 32) wdw = 32;
    if (wdw > 512) wdw = 512;
    int half_w = wdw / 2;

    cudaFuncSetAttribute(gemm_tf32, cudaFuncAttributeMaxDynamicSharedMemorySize, GS_TOTAL);
    cudaFuncSetAttribute(attn_tc, cudaFuncAttributeMaxDynamicSharedMemorySize, 2 * AST_BYTES);

    gpos_kernel<<<1, 256>>>();
    {
        int n4 = (Bc * Sc * Ec) / 4;
        round_kernel<<<(n4 + 255) / 256, 256>>>(x, xr_p, n4);
    }
    {
        int n4 = (Ec * E3) / 4;
        round_kernel<<<(n4 + 255) / 256, 256>>>(w_attn, war_p, n4);
    }
    {
        int n4 = (Ec * Ec) / 4;
        round_kernel<<<(n4 + 255) / 256, 256>>>(w_proj, wpr_p, n4);
    }

    dim3 g1(E3 / 128, (Bc * Sc) / 128);
    gemm_tf32<<<g1, 256, GS_TOTAL>>>(xr_p, war_p, b_attn, qkv_p, Bc * Sc, E3, Ec, 1);

    gather_kernel<<<16, 256>>>(qkv_p);

    dim3 ga(Sc / 64, Hc, Bc);
    attn_tc<<<ga, 128, 2 * AST_BYTES>>>(qkv_p, attn_p, half_w);

    dim3 g2(Ec / 128, (Bc * Sc) / 128);
    gemm_tf32<<<g2, 256, GS_TOTAL>>>(attn_p, wpr_p, b_proj, out, Bc * Sc, Ec, Ec, 0);
}

// round 7
// speedup vs baseline: 1.6003x; 1.2561x over previous
#include <cuda_runtime.h>
#include <cuda_fp16.h>
#include <math.h>
#include <stdint.h>

#define Bc 4
#define Sc 2048
#define Ec 768
#define Hc 12
#define Dc 64
#define E3 2304
#define NGLOB 204

// Scratch (device globals; no runtime allocation allowed)
__device__ float  g_qkv[(size_t)Bc * Sc * E3];     // [B,S,3E] tf32-rounded f32
__device__ __half g_attnh[(size_t)Bc * Sc * Ec];   // attention out, fp16
__device__ __half g_xh[(size_t)Bc * Sc * Ec];      // x fp16
__device__ __half g_waT[(size_t)E3 * Ec];          // w_attn^T [3E][E] fp16
__device__ __half g_wpT[(size_t)Ec * Ec];          // w_proj^T [E][E] fp16
__device__ float  g_Kg[16 * 256 * 64];             // gathered global K (pi-permuted 64-blocks)
__device__ float  g_Vg[16 * 256 * 64];             // gathered global V (natural)
__device__ int    g_gjpad[256];                    // global col indices, -1 pad
__device__ int    g_gstart[32];                    // per qtile: #gpos <= q0

// ---------------------------------------------------------------------------
__device__ __forceinline__ unsigned f2tf(float x) {
    unsigned r;
    asm("cvt.rna.tf32.f32 %0, %1;" : "=r"(r) : "f"(x));
    return r;
}
__device__ __forceinline__ float roundtf(float x) { return __uint_as_float(f2tf(x)); }

__device__ __forceinline__ void mma_tf32(float* d, const unsigned* a, unsigned b0, unsigned b1) {
    asm volatile(
        "mma.sync.aligned.m16n8k8.row.col.f32.tf32.tf32.f32 "
        "{%0,%1,%2,%3}, {%4,%5,%6,%7}, {%8,%9}, {%0,%1,%2,%3};"
        : "+f"(d[0]), "+f"(d[1]), "+f"(d[2]), "+f"(d[3])
        : "r"(a[0]), "r"(a[1]), "r"(a[2]), "r"(a[3]), "r"(b0), "r"(b1));
}
__device__ __forceinline__ void mma_f16(float* d, const unsigned* a, unsigned b0, unsigned b1) {
    asm volatile(
        "mma.sync.aligned.m16n8k16.row.col.f32.f16.f16.f32 "
        "{%0,%1,%2,%3}, {%4,%5,%6,%7}, {%8,%9}, {%0,%1,%2,%3};"
        : "+f"(d[0]), "+f"(d[1]), "+f"(d[2]), "+f"(d[3])
        : "r"(a[0]), "r"(a[1]), "r"(a[2]), "r"(a[3]), "r"(b0), "r"(b1));
}
__device__ __forceinline__ uint32_t smem_u32(const void* p) {
    uint32_t a;
    asm("{ .reg .u64 t; cvta.to.shared.u64 t, %1; cvt.u32.u64 %0, t; }" : "=r"(a) : "l"(p));
    return a;
}
__device__ __forceinline__ void cpa16(uint32_t dst, const void* src) {
    asm volatile("cp.async.cg.shared.global [%0], [%1], 16;" :: "r"(dst), "l"(src));
}
__device__ __forceinline__ void cpa_commit() {
    asm volatile("cp.async.commit_group;" ::: "memory");
}

// ---------------------------------------------------------------------------
__global__ void gpos_kernel() {
    int t = threadIdx.x;   // 256
    const float step = (float)((double)(Sc - 1) / (double)(NGLOB - 1));
    int j = -1;
    if (t < NGLOB) {
        if (t == NGLOB - 1) j = Sc - 1;
        else                j = (int)(__fmul_rn((float)t, step));
        if (j < 0) j = 0;
        if (j > Sc - 1) j = Sc - 1;
    }
    g_gjpad[t] = j;
    __syncthreads();
    if (t < 32) {
        int q0 = t * 64, cnt = 0;
        for (int k = 0; k < NGLOB; k++) cnt += (g_gjpad[k] <= q0) ? 1 : 0;
        g_gstart[t] = cnt;
    }
}

// x (f32) -> half, elementwise
__global__ void cvth_kernel(const float* __restrict__ in, __half* __restrict__ outp, int n4) {
    int i = blockIdx.x * blockDim.x + threadIdx.x;
    if (i < n4) {
        float4 v = ((const float4*)in)[i];
        __half2 h0 = __floats2half2_rn(v.x, v.y);
        __half2 h1 = __floats2half2_rn(v.z, v.w);
        uint2 u;
        u.x = *(unsigned*)&h0;
        u.y = *(unsigned*)&h1;
        ((uint2*)outp)[i] = u;
    }
}

// W[K][N] f32 -> WT[N][K] half (convert + transpose)
__global__ void cvtT_kernel(const float* __restrict__ W, __half* __restrict__ WT, int K, int N) {
    __shared__ float t[32][33];
    int n0 = blockIdx.x * 32, k0 = blockIdx.y * 32;
    int tx = threadIdx.x, ty = threadIdx.y;
#pragma unroll
    for (int i = 0; i < 4; i++)
        t[ty + i * 8][tx] = W[(size_t)(k0 + ty + i * 8) * N + n0 + tx];
    __syncthreads();
#pragma unroll
    for (int i = 0; i < 4; i++)
        WT[(size_t)(n0 + ty + i * 8) * K + k0 + tx] = __float2half(t[tx][ty + i * 8]);
}

// gather global-column K/V for heads 8..11 (K with 64-block pi-permutation)
__global__ __launch_bounds__(256) void gather_kernel(const float* __restrict__ qkv) {
    int blk = blockIdx.x;            // b*4 + (h-8)
    int b = blk >> 2, h = 8 + (blk & 3);
    const float* kb = qkv + (size_t)b * Sc * E3 + Ec + h * Dc;
    const float* vb = kb + Ec;
    float* Kg = g_Kg + (size_t)blk * 256 * 64;
    float* Vg = g_Vg + (size_t)blk * 256 * 64;
    int slot = threadIdx.x;
    int slo = slot & 63, t = slot >> 6;
    int pk = (slo & 56) + ((slo & 7) >> 1) + ((slo & 1) << 2);
    int jK = g_gjpad[t * 64 + pk];
    int jV = g_gjpad[slot];
    float4 z = make_float4(0.f, 0.f, 0.f, 0.f);
#pragma unroll
    for (int c16 = 0; c16 < 16; c16++) {
        float4 kv = (jK >= 0) ? *(const float4*)(kb + (size_t)jK * E3 + c16 * 4) : z;
        ((float4*)(Kg + (size_t)slot * 64))[c16] = kv;
        float4 vv = (jV >= 0) ? *(const float4*)(vb + (size_t)jV * E3 + c16 * 4) : z;
        ((float4*)(Vg + (size_t)slot * 64))[c16] = vv;
    }
}

// ---------------------------------------------------------------------------
// fp16 mma.sync GEMM (m16n8k16) with 3-stage cp.async pipeline.
// C[M,N] = A[M,K] * WT[N,K]^T + bias. A, WT fp16; accumulate f32.
// 256 threads = 8 warps (4x2), warp tile 32x64, BK=32.
// Stage: A [128][40h]=10240B + B [128][40h]=10240B = 20480B.
// ---------------------------------------------------------------------------
#define HST_BYTES 20480
#define HST_BOFF  10240
#define HGS_TOTAL (3 * HST_BYTES)

__device__ __forceinline__ void copy_stage_h(const __half* __restrict__ A, const __half* __restrict__ WT,
                                             int m0, int n0, int K, int kt,
                                             uint32_t sbase, int tid) {
    const int kb = kt * 32;
    const uint32_t sA = sbase, sB = sbase + HST_BOFF;
#pragma unroll
    for (int i = 0; i < 2; i++) {
        int idx = tid + i * 256;
        int row = idx >> 2, ch = idx & 3;
        cpa16(sA + row * 80 + ch * 16, A + (size_t)(m0 + row) * K + kb + ch * 8);
    }
#pragma unroll
    for (int i = 0; i < 2; i++) {
        int idx = tid + i * 256;
        int row = idx >> 2, ch = idx & 3;
        cpa16(sB + row * 80 + ch * 16, WT + (size_t)(n0 + row) * K + kb + ch * 8);
    }
    cpa_commit();
}

__global__ __launch_bounds__(256, 2) void gemm_f16(
    const __half* __restrict__ A, const __half* __restrict__ WT,
    const float* __restrict__ bias, float* __restrict__ C,
    int M, int N, int K, int roundOut)
{
    extern __shared__ char smem[];
    const uint32_t sb = smem_u32(smem);

    const int tid = threadIdx.x;
    const int lane = tid & 31;
    const int w = tid >> 5;
    const int g = lane >> 2, c = lane & 3;
    const int wm = (w & 3) * 32;
    const int wn = (w >> 2) * 64;
    const int m0 = blockIdx.y << 7, n0 = blockIdx.x << 7;
    const int NT = K >> 5;

    float acc[2][8][4];
#pragma unroll
    for (int mt = 0; mt < 2; mt++)
#pragma unroll
        for (int nt = 0; nt < 8; nt++)
#pragma unroll
            for (int i = 0; i < 4; i++) acc[mt][nt][i] = 0.f;

    copy_stage_h(A, WT, m0, n0, K, 0, sb, tid);
    copy_stage_h(A, WT, m0, n0, K, 1, sb + HST_BYTES, tid);
    copy_stage_h(A, WT, m0, n0, K, 2, sb + 2 * HST_BYTES, tid);

    for (int kt = 0; kt < NT; kt++) {
        asm volatile("cp.async.wait_group 2;" ::: "memory");
        __syncthreads();

        const unsigned* As = (const unsigned*)(smem + (kt % 3) * HST_BYTES);   // row stride 20 words
        const unsigned* Bs = (const unsigned*)(smem + (kt % 3) * HST_BYTES + HST_BOFF);

#pragma unroll
        for (int ks = 0; ks < 2; ks++) {
            const int wb = ks * 8;
            unsigned a[2][4];
#pragma unroll
            for (int mt = 0; mt < 2; mt++) {
                int m = wm + mt * 16 + g;
                a[mt][0] = As[m * 20 + wb + c];
                a[mt][1] = As[(m + 8) * 20 + wb + c];
                a[mt][2] = As[m * 20 + wb + 4 + c];
                a[mt][3] = As[(m + 8) * 20 + wb + 4 + c];
            }
#pragma unroll
            for (int nt = 0; nt < 8; nt++) {
                int n = wn + nt * 8 + g;
                unsigned b0 = Bs[n * 20 + wb + c];
                unsigned b1 = Bs[n * 20 + wb + 4 + c];
#pragma unroll
                for (int mt = 0; mt < 2; mt++)
                    mma_f16(acc[mt][nt], a[mt], b0, b1);
            }
        }
        __syncthreads();

        if (kt + 3 < NT) copy_stage_h(A, WT, m0, n0, K, kt + 3, sb + (kt % 3) * HST_BYTES, tid);
        else             cpa_commit();
    }

#pragma unroll
    for (int mt = 0; mt < 2; mt++) {
        int r0 = m0 + wm + mt * 16 + g;
#pragma unroll
        for (int nt = 0; nt < 8; nt++) {
            int col = n0 + wn + nt * 8 + 2 * c;
            float bv0 = bias[col], bv1 = bias[col + 1];
            float v00 = acc[mt][nt][0] + bv0, v01 = acc[mt][nt][1] + bv1;
            float v10 = acc[mt][nt][2] + bv0, v11 = acc[mt][nt][3] + bv1;
            if (roundOut) {
                v00 = roundtf(v00); v01 = roundtf(v01);
                v10 = roundtf(v10); v11 = roundtf(v11);
            }
            *(float2*)(C + (size_t)r0 * N + col) = make_float2(v00, v01);
            *(float2*)(C + (size_t)(r0 + 8) * N + col) = make_float2(v10, v11);
        }
    }
}

// ---------------------------------------------------------------------------
// Attention (R6, unchanged logic): cp.async double-buffered, tf32 mma.
// Output written as fp16 (feeds fp16 proj GEMM).
// ---------------------------------------------------------------------------
#define AKW 68
#define AVW 72
#define AST_BYTES 35840
#define AST_VOFF  17408

__device__ __forceinline__ void attn_issue(
    int it, int n_causal, int n_tiles, int kt_base, int ct0,
    const float* __restrict__ kb, const float* __restrict__ vb,
    const float* __restrict__ KgB, const float* __restrict__ VgB,
    uint32_t sbase, int tid)
{
    if (it >= n_tiles) { cpa_commit(); return; }
    const uint32_t sK = sbase, sV = sbase + AST_VOFF;
    if (it < n_causal) {
        const int k0 = (kt_base + it) << 6;
#pragma unroll
        for (int i = 0; i < 8; i++) {
            int ch = tid + i * 128;
            int slot = ch >> 4, c16 = ch & 15;
            int jk = k0 + (slot & 56) + ((slot & 7) >> 1) + ((slot & 1) << 2);
            cpa16(sK + slot * 272 + c16 * 16, kb + (size_t)jk * E3 + c16 * 4);
            cpa16(sV + slot * 288 + c16 * 16, vb + (size_t)(k0 + slot) * E3 + c16 * 4);
        }
    } else {
        const int ct = ct0 + it - n_causal;
        const float* Kt = KgB + (size_t)ct * 64 * 64;
        const float* Vt = VgB + (size_t)ct * 64 * 64;
#pragma unroll
        for (int i = 0; i < 8; i++) {
            int ch = tid + i * 128;
            int slot = ch >> 4, c16 = ch & 15;
            cpa16(sK + slot * 272 + c16 * 16, Kt + (size_t)slot * 64 + c16 * 4);
            cpa16(sV + slot * 288 + c16 * 16, Vt + (size_t)slot * 64 + c16 * 4);
        }
    }
    cpa_commit();
}

__global__ __launch_bounds__(128) void attn_tc(
    const float* __restrict__ qkv, __half* __restrict__ out, int half_w)
{
    extern __shared__ char smem[];
    const uint32_t sb = smem_u32(smem);
    const unsigned* smw = (const unsigned*)smem;

    const int qt = blockIdx.x, h = blockIdx.y, b = blockIdx.z;
    const bool is_local = (h < 8);
    const int q0 = qt << 6;
    const int tid = threadIdx.x;
    const int lane = tid & 31;
    const int w = tid >> 5;
    const int g = lane >> 2, c = lane & 3;

    const float* qb = qkv + (size_t)b * Sc * E3 + h * Dc;
    const float* kb = qb + Ec;
    const float* vb = qb + 2 * Ec;
    const float* KgB = g_Kg + (size_t)(b * 4 + (h - 8)) * 256 * 64;
    const float* VgB = g_Vg + (size_t)(b * 4 + (h - 8)) * 256 * 64;

    const int r0 = q0 + 16 * w + g;
    const int r1 = r0 + 8;
    const float* qrow0 = qb + (size_t)r0 * E3;
    const float* qrow1 = qrow0 + (size_t)8 * E3;
    unsigned qa[8][4];
#pragma unroll
    for (int ks = 0; ks < 8; ks++) {
        qa[ks][0] = __float_as_uint(qrow0[ks * 8 + c] * 0.125f);
        qa[ks][1] = __float_as_uint(qrow1[ks * 8 + c] * 0.125f);
        qa[ks][2] = __float_as_uint(qrow0[ks * 8 + c + 4] * 0.125f);
        qa[ks][3] = __float_as_uint(qrow1[ks * 8 + c + 4] * 0.125f);
    }

    float o[8][4];
#pragma unroll
    for (int nt = 0; nt < 8; nt++)
#pragma unroll
        for (int i = 0; i < 4; i++) o[nt][i] = 0.f;
    float m0 = -1e30f, m1 = -1e30f, l0 = 0.f, l1 = 0.f;

    int kt_base, n_causal, n_tiles, ct0 = 0;
    if (is_local) {
        int lo = (q0 - half_w) >> 6;
        kt_base = lo > 0 ? lo : 0;
        n_causal = qt - kt_base + 1;
        n_tiles = n_causal;
    } else {
        kt_base = 0;
        n_causal = qt + 1;
        ct0 = g_gstart[qt] >> 6;
        n_tiles = n_causal + (4 - ct0);
    }

    attn_issue(0, n_causal, n_tiles, kt_base, ct0, kb, vb, KgB, VgB, sb, tid);
    attn_issue(1, n_causal, n_tiles, kt_base, ct0, kb, vb, KgB, VgB, sb + AST_BYTES, tid);

    for (int it = 0; it < n_tiles; it++) {
        asm volatile("cp.async.wait_group 1;" ::: "memory");
        __syncthreads();

        const unsigned* Ks = smw + (it & 1) * (AST_BYTES / 4);
        const unsigned* Vs = Ks + 64 * AKW;
        const bool compact = (!is_local) && (it >= n_causal);
        const int k0 = (kt_base + it) << 6;
        const int ctb = compact ? (ct0 + it - n_causal) * 64 : 0;

        float s[8][4];
#pragma unroll
        for (int nt = 0; nt < 8; nt++)
#pragma unroll
            for (int i = 0; i < 4; i++) s[nt][i] = 0.f;
#pragma unroll
        for (int ks = 0; ks < 8; ks++) {
            const int kk = ks * 8;
#pragma unroll
            for (int nt = 0; nt < 8; nt++) {
                unsigned b0 = Ks[(nt * 8 + g) * AKW + kk + c];
                unsigned b1 = Ks[(nt * 8 + g) * AKW + kk + c + 4];
                mma_tf32(s[nt], qa[ks], b0, b1);
            }
        }

        if (is_local) {
#pragma unroll
            for (int nt = 0; nt < 8; nt++) {
                int jA = k0 + 8 * nt + c, jB = jA + 4;
                s[nt][0] = (jA <= r0 && jA >= r0 - half_w) ? s[nt][0] : -1e9f;
                s[nt][1] = (jB <= r0 && jB >= r0 - half_w) ? s[nt][1] : -1e9f;
                s[nt][2] = (jA <= r1 && jA >= r1 - half_w) ? s[nt][2] : -1e9f;
                s[nt][3] = (jB <= r1 && jB >= r1 - half_w) ? s[nt][3] : -1e9f;
            }
        } else if (!compact) {
#pragma unroll
            for (int nt = 0; nt < 8; nt++) {
                int jA = k0 + 8 * nt + c, jB = jA + 4;
                s[nt][0] = (jA <= r0) ? s[nt][0] : -1e9f;
                s[nt][1] = (jB <= r0) ? s[nt][1] : -1e9f;
                s[nt][2] = (jA <= r1) ? s[nt][2] : -1e9f;
                s[nt][3] = (jB <= r1) ? s[nt][3] : -1e9f;
            }
        } else {
#pragma unroll
            for (int nt = 0; nt < 8; nt++) {
                int jA = g_gjpad[ctb + 8 * nt + c];
                int jB = g_gjpad[ctb + 8 * nt + c + 4];
                s[nt][0] = (jA > r0) ? s[nt][0] : -1e9f;
                s[nt][1] = (jB > r0) ? s[nt][1] : -1e9f;
                s[nt][2] = (jA > r1) ? s[nt][2] : -1e9f;
                s[nt][3] = (jB > r1) ? s[nt][3] : -1e9f;
            }
        }

        float mx0 = -1e30f, mx1 = -1e30f;
#pragma unroll
        for (int nt = 0; nt < 8; nt++) {
            mx0 = fmaxf(mx0, fmaxf(s[nt][0], s[nt][1]));
            mx1 = fmaxf(mx1, fmaxf(s[nt][2], s[nt][3]));
        }
        mx0 = fmaxf(mx0, __shfl_xor_sync(0xffffffffu, mx0, 1));
        mx0 = fmaxf(mx0, __shfl_xor_sync(0xffffffffu, mx0, 2));
        mx1 = fmaxf(mx1, __shfl_xor_sync(0xffffffffu, mx1, 1));
        mx1 = fmaxf(mx1, __shfl_xor_sync(0xffffffffu, mx1, 2));

        float mn0 = fmaxf(m0, mx0), mn1 = fmaxf(m1, mx1);
        float f0 = __expf(m0 - mn0), f1 = __expf(m1 - mn1);
        m0 = mn0; m1 = mn1;

        float ps0 = 0.f, ps1 = 0.f;
#pragma unroll
        for (int nt = 0; nt < 8; nt++) {
            s[nt][0] = __expf(s[nt][0] - mn0);
            s[nt][1] = __expf(s[nt][1] - mn0);
            s[nt][2] = __expf(s[nt][2] - mn1);
            s[nt][3] = __expf(s[nt][3] - mn1);
            ps0 += s[nt][0] + s[nt][1];
            ps1 += s[nt][2] + s[nt][3];
            o[nt][0] *= f0; o[nt][1] *= f0;
            o[nt][2] *= f1; o[nt][3] *= f1;
        }
        ps0 += __shfl_xor_sync(0xffffffffu, ps0, 1);
        ps0 += __shfl_xor_sync(0xffffffffu, ps0, 2);
        ps1 += __shfl_xor_sync(0xffffffffu, ps1, 1);
        ps1 += __shfl_xor_sync(0xffffffffu, ps1, 2);
        l0 = l0 * f0 + ps0;
        l1 = l1 * f1 + ps1;

#pragma unroll
        for (int ktile = 0; ktile < 8; ktile++) {
            unsigned pa[4];
            pa[0] = f2tf(s[ktile][0]);
            pa[1] = f2tf(s[ktile][2]);
            pa[2] = f2tf(s[ktile][1]);
            pa[3] = f2tf(s[ktile][3]);
#pragma unroll
            for (int nt = 0; nt < 8; nt++) {
                unsigned b0 = Vs[(8 * ktile + c) * AVW + 8 * nt + g];
                unsigned b1 = Vs[(8 * ktile + c + 4) * AVW + 8 * nt + g];
                mma_tf32(o[nt], pa, b0, b1);
            }
        }
        __syncthreads();

        attn_issue(it + 2, n_causal, n_tiles, kt_base, ct0, kb, vb, KgB, VgB,
                   sb + (it & 1) * AST_BYTES, tid);
    }

    // write [B,S,H*D] fp16 (A operand of proj GEMM)
    float inv0 = 1.0f / l0, inv1 = 1.0f / l1;
    __half* ob0 = out + (size_t)(b * Sc + r0) * Ec + h * Dc;
    __half* ob1 = out + (size_t)(b * Sc + r1) * Ec + h * Dc;
#pragma unroll
    for (int nt = 0; nt < 8; nt++) {
        int d = 8 * nt + 2 * c;
        *(__half2*)(ob0 + d) = __floats2half2_rn(o[nt][0] * inv0, o[nt][1] * inv0);
        *(__half2*)(ob1 + d) = __floats2half2_rn(o[nt][2] * inv1, o[nt][3] * inv1);
    }
}

// ---------------------------------------------------------------------------
extern "C" void kernel_launch(void* const* d_in, const int* in_sizes, int n_in,
                              void* d_out, int out_size) {
    const float* x      = (const float*)d_in[0];
    const float* w_attn = (const float*)d_in[1];
    const float* b_attn = (const float*)d_in[2];
    const float* w_proj = (const float*)d_in[3];
    const float* b_proj = (const float*)d_in[4];
    float* out = (float*)d_out;

    float *qkv_p;
    __half *attnh_p, *xh_p, *waT_p, *wpT_p;
    cudaGetSymbolAddress((void**)&qkv_p, g_qkv);
    cudaGetSymbolAddress((void**)&attnh_p, g_attnh);
    cudaGetSymbolAddress((void**)&xh_p, g_xh);
    cudaGetSymbolAddress((void**)&waT_p, g_waT);
    cudaGetSymbolAddress((void**)&wpT_p, g_wpT);

    int wdw = (int)(128.0 * sqrt((double)Sc / 128.0));
    if (wdw < 32) wdw = 32;
    if (wdw > 512) wdw = 512;
    int half_w = wdw / 2;

    cudaFuncSetAttribute(gemm_f16, cudaFuncAttributeMaxDynamicSharedMemorySize, HGS_TOTAL);
    cudaFuncSetAttribute(attn_tc, cudaFuncAttributeMaxDynamicSharedMemorySize, 2 * AST_BYTES);

    gpos_kernel<<<1, 256>>>();
    {
        int n4 = (Bc * Sc * Ec) / 4;
        cvth_kernel<<<(n4 + 255) / 256, 256>>>(x, xh_p, n4);
    }
    {
        dim3 gt(E3 / 32, Ec / 32);
        cvtT_kernel<<<gt, dim3(32, 8)>>>(w_attn, waT_p, Ec, E3);
    }
    {
        dim3 gt(Ec / 32, Ec / 32);
        cvtT_kernel<<<gt, dim3(32, 8)>>>(w_proj, wpT_p, Ec, Ec);
    }

    dim3 g1(E3 / 128, (Bc * Sc) / 128);
    gemm_f16<<<g1, 256, HGS_TOTAL>>>(xh_p, waT_p, b_attn, qkv_p, Bc * Sc, E3, Ec, 1);

    gather_kernel<<<16, 256>>>(qkv_p);

    dim3 ga(Sc / 64, Hc, Bc);
    attn_tc<<<ga, 128, 2 * AST_BYTES>>>(qkv_p, attnh_p, half_w);

    dim3 g2(Ec / 128, (Bc * Sc) / 128);
    gemm_f16<<<g2, 256, HGS_TOTAL>>>(attnh_p, wpT_p, b_proj, out, Bc * Sc, Ec, Ec, 0);
}

// round 8
// speedup vs baseline: 1.8932x; 1.1830x over previous
#include <cuda_runtime.h>
#include <cuda_fp16.h>
#include <math.h>
#include <stdint.h>

#define Bc 4
#define Sc 2048
#define Ec 768
#define Hc 12
#define Dc 64
#define E3 2304
#define NGLOB 204

// Scratch (device globals; no runtime allocation allowed)
__device__ __half g_qkvh[(size_t)Bc * Sc * E3];    // [B,S,3E] fp16
__device__ __half g_attnh[(size_t)Bc * Sc * Ec];   // attention out fp16
__device__ __half g_xh[(size_t)Bc * Sc * Ec];      // x fp16
__device__ __half g_waT[(size_t)E3 * Ec];          // w_attn^T fp16
__device__ __half g_wpT[(size_t)Ec * Ec];          // w_proj^T fp16
__device__ __half g_vTh[(size_t)Bc * Hc * Dc * Sc];// V transposed [b,h,d,s] fp16
__device__ __half g_Kgh[16 * 256 * 64];            // compact global K [blk][slot][d]
__device__ __half g_VgTh[16 * 64 * 256];           // compact global V^T [blk][d][slot]
__device__ int    g_gjpad[256];                    // global col indices, -1 pad
__device__ int    g_gstart[32];                    // per qtile: #gpos <= q0

// ---------------------------------------------------------------------------
__device__ __forceinline__ void mma_f16(float* d, const unsigned* a, unsigned b0, unsigned b1) {
    asm volatile(
        "mma.sync.aligned.m16n8k16.row.col.f32.f16.f16.f32 "
        "{%0,%1,%2,%3}, {%4,%5,%6,%7}, {%8,%9}, {%0,%1,%2,%3};"
        : "+f"(d[0]), "+f"(d[1]), "+f"(d[2]), "+f"(d[3])
        : "r"(a[0]), "r"(a[1]), "r"(a[2]), "r"(a[3]), "r"(b0), "r"(b1));
}
__device__ __forceinline__ uint32_t smem_u32(const void* p) {
    uint32_t a;
    asm("{ .reg .u64 t; cvta.to.shared.u64 t, %1; cvt.u32.u64 %0, t; }" : "=r"(a) : "l"(p));
    return a;
}
__device__ __forceinline__ void cpa16(uint32_t dst, const void* src) {
    asm volatile("cp.async.cg.shared.global [%0], [%1], 16;" :: "r"(dst), "l"(src));
}
__device__ __forceinline__ void cpa_commit() {
    asm volatile("cp.async.commit_group;" ::: "memory");
}
__device__ __forceinline__ unsigned h2scale8(unsigned v) {   // *0.125 (exact pow2)
    __half2 a = *(__half2*)&v;
    a = __hmul2(a, __half2half2(__ushort_as_half((unsigned short)0x3000)));
    return *(unsigned*)&a;
}
__device__ __forceinline__ unsigned packh2(float lo, float hi) {
    __half2 h = __floats2half2_rn(lo, hi);
    return *(unsigned*)&h;
}

// ---------------------------------------------------------------------------
__global__ void gpos_kernel() {
    int t = threadIdx.x;   // 256
    const float step = (float)((double)(Sc - 1) / (double)(NGLOB - 1));
    int j = -1;
    if (t < NGLOB) {
        if (t == NGLOB - 1) j = Sc - 1;
        else                j = (int)(__fmul_rn((float)t, step));
        if (j < 0) j = 0;
        if (j > Sc - 1) j = Sc - 1;
    }
    g_gjpad[t] = j;
    __syncthreads();
    if (t < 32) {
        int q0 = t * 64, cnt = 0;
        for (int k = 0; k < NGLOB; k++) cnt += (g_gjpad[k] <= q0) ? 1 : 0;
        g_gstart[t] = cnt;
    }
}

__global__ void cvth_kernel(const float* __restrict__ in, __half* __restrict__ outp, int n4) {
    int i = blockIdx.x * blockDim.x + threadIdx.x;
    if (i < n4) {
        float4 v = ((const float4*)in)[i];
        __half2 h0 = __floats2half2_rn(v.x, v.y);
        __half2 h1 = __floats2half2_rn(v.z, v.w);
        uint2 u;
        u.x = *(unsigned*)&h0;
        u.y = *(unsigned*)&h1;
        ((uint2*)outp)[i] = u;
    }
}

__global__ void cvtT_kernel(const float* __restrict__ W, __half* __restrict__ WT, int K, int N) {
    __shared__ float t[32][33];
    int n0 = blockIdx.x * 32, k0 = blockIdx.y * 32;
    int tx = threadIdx.x, ty = threadIdx.y;
#pragma unroll
    for (int i = 0; i < 4; i++)
        t[ty + i * 8][tx] = W[(size_t)(k0 + ty + i * 8) * N + n0 + tx];
    __syncthreads();
#pragma unroll
    for (int i = 0; i < 4; i++)
        WT[(size_t)(n0 + ty + i * 8) * K + k0 + tx] = __float2half(t[tx][ty + i * 8]);
}

// V [token][d] (inside qkv) -> vT [b,h,d,token]
__global__ __launch_bounds__(256) void vT_kernel(const __half* __restrict__ qkv,
                                                 __half* __restrict__ vT) {
    __shared__ __half t[64][72];
    int blk = blockIdx.x;
    int st = blk & 31, bh = blk >> 5;
    int b = bh / Hc, h = bh % Hc;
    const __half* vb = qkv + (size_t)b * Sc * E3 + 2 * Ec + h * Dc;
    int s0 = st << 6;
    int tid = threadIdx.x;
#pragma unroll
    for (int i = 0; i < 2; i++) {
        int idx = tid + i * 256;
        int row = idx >> 3, c16 = idx & 7;
        uint4 v = *(const uint4*)(vb + (size_t)(s0 + row) * E3 + c16 * 8);
        *(uint4*)&t[row][c16 * 8] = v;
    }
    __syncthreads();
    const unsigned short* ts = (const unsigned short*)&t[0][0];
#pragma unroll
    for (int i = 0; i < 2; i++) {
        int idx = tid + i * 256;
        int d = idx >> 3, seg = (idx & 7) * 8;
        uint4 u;
        unsigned short* us = (unsigned short*)&u;
#pragma unroll
        for (int j = 0; j < 8; j++) us[j] = ts[(seg + j) * 72 + d];
        *(uint4*)(vT + ((size_t)bh * Dc + d) * Sc + s0 + seg) = u;
    }
}

// gather compact global K (natural) and V^T for heads 8..11
__global__ __launch_bounds__(256) void gather_kernel(const __half* __restrict__ qkv,
                                                     const __half* __restrict__ vT) {
    int blk = blockIdx.x;            // b*4 + (h-8)
    int b = blk >> 2, h = 8 + (blk & 3);
    const __half* kb = qkv + (size_t)b * Sc * E3 + Ec + h * Dc;
    __half* Kg = g_Kgh + (size_t)blk * 256 * 64;
    __half* VgT = g_VgTh + (size_t)blk * 64 * 256;
    int tid = threadIdx.x;
#pragma unroll
    for (int i = 0; i < 8; i++) {
        int idx = tid + i * 256;
        int slot = idx >> 3, c16 = idx & 7;
        int j = g_gjpad[slot];
        uint4 v = make_uint4(0u, 0u, 0u, 0u);
        if (j >= 0) v = *(const uint4*)(kb + (size_t)j * E3 + c16 * 8);
        *(uint4*)(Kg + (size_t)slot * 64 + c16 * 8) = v;
    }
    int j = g_gjpad[tid];
    const __half* vrow = vT + (size_t)(b * Hc + h) * Dc * Sc;
    __half z = __ushort_as_half((unsigned short)0);
#pragma unroll
    for (int d = 0; d < 64; d++) {
        __half val = (j >= 0) ? vrow[(size_t)d * Sc + j] : z;
        VgT[d * 256 + tid] = val;
    }
}

// ---------------------------------------------------------------------------
// fp16 mma.sync GEMM (m16n8k16) with 3-stage cp.async pipeline.
// C = A[M,K] * WT[N,K]^T + bias. Output: f32 or fp16 (halfOut).
// ---------------------------------------------------------------------------
#define HST_BYTES 20480
#define HST_BOFF  10240
#define HGS_TOTAL (3 * HST_BYTES)

__device__ __forceinline__ void copy_stage_h(const __half* __restrict__ A, const __half* __restrict__ WT,
                                             int m0, int n0, int K, int kt,
                                             uint32_t sbase, int tid) {
    const int kb = kt * 32;
    const uint32_t sA = sbase, sB = sbase + HST_BOFF;
#pragma unroll
    for (int i = 0; i < 2; i++) {
        int idx = tid + i * 256;
        int row = idx >> 2, ch = idx & 3;
        cpa16(sA + row * 80 + ch * 16, A + (size_t)(m0 + row) * K + kb + ch * 8);
    }
#pragma unroll
    for (int i = 0; i < 2; i++) {
        int idx = tid + i * 256;
        int row = idx >> 2, ch = idx & 3;
        cpa16(sB + row * 80 + ch * 16, WT + (size_t)(n0 + row) * K + kb + ch * 8);
    }
    cpa_commit();
}

__global__ __launch_bounds__(256, 2) void gemm_f16(
    const __half* __restrict__ A, const __half* __restrict__ WT,
    const float* __restrict__ bias, float* __restrict__ Cf, __half* __restrict__ Ch,
    int M, int N, int K, int halfOut)
{
    extern __shared__ char smem[];
    const uint32_t sb = smem_u32(smem);

    const int tid = threadIdx.x;
    const int lane = tid & 31;
    const int w = tid >> 5;
    const int g = lane >> 2, c = lane & 3;
    const int wm = (w & 3) * 32;
    const int wn = (w >> 2) * 64;
    const int m0 = blockIdx.y << 7, n0 = blockIdx.x << 7;
    const int NT = K >> 5;

    float acc[2][8][4];
#pragma unroll
    for (int mt = 0; mt < 2; mt++)
#pragma unroll
        for (int nt = 0; nt < 8; nt++)
#pragma unroll
            for (int i = 0; i < 4; i++) acc[mt][nt][i] = 0.f;

    copy_stage_h(A, WT, m0, n0, K, 0, sb, tid);
    copy_stage_h(A, WT, m0, n0, K, 1, sb + HST_BYTES, tid);
    copy_stage_h(A, WT, m0, n0, K, 2, sb + 2 * HST_BYTES, tid);

    for (int kt = 0; kt < NT; kt++) {
        asm volatile("cp.async.wait_group 2;" ::: "memory");
        __syncthreads();

        const unsigned* As = (const unsigned*)(smem + (kt % 3) * HST_BYTES);
        const unsigned* Bs = (const unsigned*)(smem + (kt % 3) * HST_BYTES + HST_BOFF);

#pragma unroll
        for (int ks = 0; ks < 2; ks++) {
            const int wb = ks * 8;
            unsigned a[2][4];
#pragma unroll
            for (int mt = 0; mt < 2; mt++) {
                int m = wm + mt * 16 + g;
                a[mt][0] = As[m * 20 + wb + c];
                a[mt][1] = As[(m + 8) * 20 + wb + c];
                a[mt][2] = As[m * 20 + wb + 4 + c];
                a[mt][3] = As[(m + 8) * 20 + wb + 4 + c];
            }
#pragma unroll
            for (int nt = 0; nt < 8; nt++) {
                int n = wn + nt * 8 + g;
                unsigned b0 = Bs[n * 20 + wb + c];
                unsigned b1 = Bs[n * 20 + wb + 4 + c];
#pragma unroll
                for (int mt = 0; mt < 2; mt++)
                    mma_f16(acc[mt][nt], a[mt], b0, b1);
            }
        }
        __syncthreads();

        if (kt + 3 < NT) copy_stage_h(A, WT, m0, n0, K, kt + 3, sb + (kt % 3) * HST_BYTES, tid);
        else             cpa_commit();
    }

#pragma unroll
    for (int mt = 0; mt < 2; mt++) {
        int r0 = m0 + wm + mt * 16 + g;
#pragma unroll
        for (int nt = 0; nt < 8; nt++) {
            int col = n0 + wn + nt * 8 + 2 * c;
            float bv0 = bias[col], bv1 = bias[col + 1];
            float v00 = acc[mt][nt][0] + bv0, v01 = acc[mt][nt][1] + bv1;
            float v10 = acc[mt][nt][2] + bv0, v11 = acc[mt][nt][3] + bv1;
            if (halfOut) {
                __half2 h0 = __floats2half2_rn(v00, v01);
                __half2 h1 = __floats2half2_rn(v10, v11);
                *(__half2*)(Ch + (size_t)r0 * N + col) = h0;
                *(__half2*)(Ch + (size_t)(r0 + 8) * N + col) = h1;
            } else {
                *(float2*)(Cf + (size_t)r0 * N + col) = make_float2(v00, v01);
                *(float2*)(Cf + (size_t)(r0 + 8) * N + col) = make_float2(v10, v11);
            }
        }
    }
}

// ---------------------------------------------------------------------------
// fp16 attention: m16n8k16 for QK and PV. K natural [key][d], V transposed
// [d][key] in smem (rows 144B, stride 36 words). cp.async double-buffered.
// ---------------------------------------------------------------------------
#define AROWW 36             // row stride in words (72 halfs = 144B)
#define AST_BYTES 18432      // 64*144 (K) + 64*144 (Vt)
#define AST_VOFF  9216

__device__ __forceinline__ void attn_issue(
    int it, int n_causal, int n_tiles, int kt_base, int ct0,
    const __half* __restrict__ kb, const __half* __restrict__ vTb,
    const __half* __restrict__ KgB, const __half* __restrict__ VgTB,
    uint32_t sbase, int tid)
{
    if (it >= n_tiles) { cpa_commit(); return; }
    const uint32_t sK = sbase, sV = sbase + AST_VOFF;
    if (it < n_causal) {
        const int k0 = (kt_base + it) << 6;
#pragma unroll
        for (int i = 0; i < 4; i++) {
            int idx = tid + i * 128;
            int slot = idx >> 3, c16 = idx & 7;
            cpa16(sK + slot * 144 + c16 * 16, kb + (size_t)(k0 + slot) * E3 + c16 * 8);
            cpa16(sV + slot * 144 + c16 * 16, vTb + (size_t)slot * Sc + k0 + c16 * 8);
        }
    } else {
        const int ct = ct0 + it - n_causal;
        const __half* Kt = KgB + (size_t)ct * 64 * 64;
#pragma unroll
        for (int i = 0; i < 4; i++) {
            int idx = tid + i * 128;
            int slot = idx >> 3, c16 = idx & 7;
            cpa16(sK + slot * 144 + c16 * 16, Kt + (size_t)slot * 64 + c16 * 8);
            cpa16(sV + slot * 144 + c16 * 16, VgTB + (size_t)slot * 256 + ct * 64 + c16 * 8);
        }
    }
    cpa_commit();
}

__global__ __launch_bounds__(128) void attn_tc(
    const __half* __restrict__ qkv, __half* __restrict__ out, int half_w)
{
    extern __shared__ char smem[];
    const uint32_t sb = smem_u32(smem);
    const unsigned* smw = (const unsigned*)smem;

    const int qt = blockIdx.x, h = blockIdx.y, b = blockIdx.z;
    const bool is_local = (h < 8);
    const int q0 = qt << 6;
    const int tid = threadIdx.x;
    const int lane = tid & 31;
    const int w = tid >> 5;
    const int g = lane >> 2, c = lane & 3;

    const __half* qb = qkv + (size_t)b * Sc * E3 + h * Dc;
    const __half* kb = qb + Ec;
    const __half* vTb = g_vTh + (size_t)(b * Hc + h) * Dc * Sc;
    const __half* KgB = g_Kgh + (size_t)(b * 4 + (h - 8)) * 256 * 64;
    const __half* VgTB = g_VgTh + (size_t)(b * 4 + (h - 8)) * 64 * 256;

    const int r0 = q0 + 16 * w + g;
    const int r1 = r0 + 8;

    // Q fragments (scaled by 1/8, exact pow2)
    const unsigned* qw0 = (const unsigned*)(qb + (size_t)r0 * E3);
    const unsigned* qw1 = (const unsigned*)(qb + (size_t)r1 * E3);
    unsigned qa[4][4];
#pragma unroll
    for (int ks = 0; ks < 4; ks++) {
        qa[ks][0] = h2scale8(qw0[8 * ks + c]);
        qa[ks][1] = h2scale8(qw1[8 * ks + c]);
        qa[ks][2] = h2scale8(qw0[8 * ks + 4 + c]);
        qa[ks][3] = h2scale8(qw1[8 * ks + 4 + c]);
    }

    float o[8][4];
#pragma unroll
    for (int nt = 0; nt < 8; nt++)
#pragma unroll
        for (int i = 0; i < 4; i++) o[nt][i] = 0.f;
    float m0 = -1e30f, m1 = -1e30f, l0 = 0.f, l1 = 0.f;

    int kt_base, n_causal, n_tiles, ct0 = 0;
    if (is_local) {
        int lo = (q0 - half_w) >> 6;
        kt_base = lo > 0 ? lo : 0;
        n_causal = qt - kt_base + 1;
        n_tiles = n_causal;
    } else {
        kt_base = 0;
        n_causal = qt + 1;
        ct0 = g_gstart[qt] >> 6;
        n_tiles = n_causal + (4 - ct0);
    }

    attn_issue(0, n_causal, n_tiles, kt_base, ct0, kb, vTb, KgB, VgTB, sb, tid);
    attn_issue(1, n_causal, n_tiles, kt_base, ct0, kb, vTb, KgB, VgTB, sb + AST_BYTES, tid);

    for (int it = 0; it < n_tiles; it++) {
        asm volatile("cp.async.wait_group 1;" ::: "memory");
        __syncthreads();

        const unsigned* Ks = smw + (it & 1) * (AST_BYTES / 4);
        const unsigned* Vs = Ks + 64 * AROWW;
        const bool compact = (!is_local) && (it >= n_causal);
        const int k0 = (kt_base + it) << 6;
        const int ctb = compact ? (ct0 + it - n_causal) * 64 : 0;

        // QK^T (4 k-steps of 16 d)
        float s[8][4];
#pragma unroll
        for (int nt = 0; nt < 8; nt++)
#pragma unroll
            for (int i = 0; i < 4; i++) s[nt][i] = 0.f;
#pragma unroll
        for (int ks = 0; ks < 4; ks++) {
#pragma unroll
            for (int nt = 0; nt < 8; nt++) {
                const unsigned* kr = Ks + (nt * 8 + g) * AROWW + 8 * ks;
                mma_f16(s[nt], qa[ks], kr[c], kr[4 + c]);
            }
        }

        // mask: cols per lane = 8nt+2c, 8nt+2c+1
        if (is_local) {
#pragma unroll
            for (int nt = 0; nt < 8; nt++) {
                int jA = k0 + 8 * nt + 2 * c, jB = jA + 1;
                s[nt][0] = (jA <= r0 && jA >= r0 - half_w) ? s[nt][0] : -1e9f;
                s[nt][1] = (jB <= r0 && jB >= r0 - half_w) ? s[nt][1] : -1e9f;
                s[nt][2] = (jA <= r1 && jA >= r1 - half_w) ? s[nt][2] : -1e9f;
                s[nt][3] = (jB <= r1 && jB >= r1 - half_w) ? s[nt][3] : -1e9f;
            }
        } else if (!compact) {
#pragma unroll
            for (int nt = 0; nt < 8; nt++) {
                int jA = k0 + 8 * nt + 2 * c, jB = jA + 1;
                s[nt][0] = (jA <= r0) ? s[nt][0] : -1e9f;
                s[nt][1] = (jB <= r0) ? s[nt][1] : -1e9f;
                s[nt][2] = (jA <= r1) ? s[nt][2] : -1e9f;
                s[nt][3] = (jB <= r1) ? s[nt][3] : -1e9f;
            }
        } else {
#pragma unroll
            for (int nt = 0; nt < 8; nt++) {
                int jA = g_gjpad[ctb + 8 * nt + 2 * c];
                int jB = g_gjpad[ctb + 8 * nt + 2 * c + 1];
                s[nt][0] = (jA > r0) ? s[nt][0] : -1e9f;
                s[nt][1] = (jB > r0) ? s[nt][1] : -1e9f;
                s[nt][2] = (jA > r1) ? s[nt][2] : -1e9f;
                s[nt][3] = (jB > r1) ? s[nt][3] : -1e9f;
            }
        }

        // online softmax (rows r0: regs 0,1; r1: regs 2,3), reduce over c lanes
        float mx0 = -1e30f, mx1 = -1e30f;
#pragma unroll
        for (int nt = 0; nt < 8; nt++) {
            mx0 = fmaxf(mx0, fmaxf(s[nt][0], s[nt][1]));
            mx1 = fmaxf(mx1, fmaxf(s[nt][2], s[nt][3]));
        }
        mx0 = fmaxf(mx0, __shfl_xor_sync(0xffffffffu, mx0, 1));
        mx0 = fmaxf(mx0, __shfl_xor_sync(0xffffffffu, mx0, 2));
        mx1 = fmaxf(mx1, __shfl_xor_sync(0xffffffffu, mx1, 1));
        mx1 = fmaxf(mx1, __shfl_xor_sync(0xffffffffu, mx1, 2));

        float mn0 = fmaxf(m0, mx0), mn1 = fmaxf(m1, mx1);
        float f0 = __expf(m0 - mn0), f1 = __expf(m1 - mn1);
        m0 = mn0; m1 = mn1;

        float ps0 = 0.f, ps1 = 0.f;
#pragma unroll
        for (int nt = 0; nt < 8; nt++) {
            s[nt][0] = __expf(s[nt][0] - mn0);
            s[nt][1] = __expf(s[nt][1] - mn0);
            s[nt][2] = __expf(s[nt][2] - mn1);
            s[nt][3] = __expf(s[nt][3] - mn1);
            ps0 += s[nt][0] + s[nt][1];
            ps1 += s[nt][2] + s[nt][3];
            o[nt][0] *= f0; o[nt][1] *= f0;
            o[nt][2] *= f1; o[nt][3] *= f1;
        }
        ps0 += __shfl_xor_sync(0xffffffffu, ps0, 1);
        ps0 += __shfl_xor_sync(0xffffffffu, ps0, 2);
        ps1 += __shfl_xor_sync(0xffffffffu, ps1, 1);
        ps1 += __shfl_xor_sync(0xffffffffu, ps1, 2);
        l0 = l0 * f0 + ps0;
        l1 = l1 * f1 + ps1;

        // PV: A-fragments come straight from score regs (natural f16 layout)
#pragma unroll
        for (int t2 = 0; t2 < 4; t2++) {
            unsigned pa[4];
            pa[0] = packh2(s[2 * t2][0], s[2 * t2][1]);
            pa[1] = packh2(s[2 * t2][2], s[2 * t2][3]);
            pa[2] = packh2(s[2 * t2 + 1][0], s[2 * t2 + 1][1]);
            pa[3] = packh2(s[2 * t2 + 1][2], s[2 * t2 + 1][3]);
#pragma unroll
            for (int nt = 0; nt < 8; nt++) {
                const unsigned* vr = Vs + (nt * 8 + g) * AROWW + 8 * t2;
                mma_f16(o[nt], pa, vr[c], vr[4 + c]);
            }
        }
        __syncthreads();

        attn_issue(it + 2, n_causal, n_tiles, kt_base, ct0, kb, vTb, KgB, VgTB,
                   sb + (it & 1) * AST_BYTES, tid);
    }

    // write [B,S,H*D] fp16
    float inv0 = 1.0f / l0, inv1 = 1.0f / l1;
    __half* ob0 = out + (size_t)(b * Sc + r0) * Ec + h * Dc;
    __half* ob1 = out + (size_t)(b * Sc + r1) * Ec + h * Dc;
#pragma unroll
    for (int nt = 0; nt < 8; nt++) {
        int d = 8 * nt + 2 * c;
        *(__half2*)(ob0 + d) = __floats2half2_rn(o[nt][0] * inv0, o[nt][1] * inv0);
        *(__half2*)(ob1 + d) = __floats2half2_rn(o[nt][2] * inv1, o[nt][3] * inv1);
    }
}

// ---------------------------------------------------------------------------
extern "C" void kernel_launch(void* const* d_in, const int* in_sizes, int n_in,
                              void* d_out, int out_size) {
    const float* x      = (const float*)d_in[0];
    const float* w_attn = (const float*)d_in[1];
    const float* b_attn = (const float*)d_in[2];
    const float* w_proj = (const float*)d_in[3];
    const float* b_proj = (const float*)d_in[4];
    float* out = (float*)d_out;

    __half *qkvh_p, *attnh_p, *xh_p, *waT_p, *wpT_p, *vT_p;
    cudaGetSymbolAddress((void**)&qkvh_p, g_qkvh);
    cudaGetSymbolAddress((void**)&attnh_p, g_attnh);
    cudaGetSymbolAddress((void**)&xh_p, g_xh);
    cudaGetSymbolAddress((void**)&waT_p, g_waT);
    cudaGetSymbolAddress((void**)&wpT_p, g_wpT);
    cudaGetSymbolAddress((void**)&vT_p, g_vTh);

    int wdw = (int)(128.0 * sqrt((double)Sc / 128.0));
    if (wdw < 32) wdw = 32;
    if (wdw > 512) wdw = 512;
    int half_w = wdw / 2;

    cudaFuncSetAttribute(gemm_f16, cudaFuncAttributeMaxDynamicSharedMemorySize, HGS_TOTAL);
    cudaFuncSetAttribute(attn_tc, cudaFuncAttributeMaxDynamicSharedMemorySize, 2 * AST_BYTES);

    gpos_kernel<<<1, 256>>>();
    {
        int n4 = (Bc * Sc * Ec) / 4;
        cvth_kernel<<<(n4 + 255) / 256, 256>>>(x, xh_p, n4);
    }
    {
        dim3 gt(E3 / 32, Ec / 32);
        cvtT_kernel<<<gt, dim3(32, 8)>>>(w_attn, waT_p, Ec, E3);
    }
    {
        dim3 gt(Ec / 32, Ec / 32);
        cvtT_kernel<<<gt, dim3(32, 8)>>>(w_proj, wpT_p, Ec, Ec);
    }

    dim3 g1(E3 / 128, (Bc * Sc) / 128);
    gemm_f16<<<g1, 256, HGS_TOTAL>>>(xh_p, waT_p, b_attn, nullptr, qkvh_p,
                                     Bc * Sc, E3, Ec, 1);

    vT_kernel<<<Bc * Hc * 32, 256>>>(qkvh_p, vT_p);
    gather_kernel<<<16, 256>>>(qkvh_p, vT_p);

    dim3 ga(Sc / 64, Hc, Bc);
    attn_tc<<<ga, 128, 2 * AST_BYTES>>>(qkvh_p, attnh_p, half_w);

    dim3 g2(Ec / 128, (Bc * Sc) / 128);
    gemm_f16<<<g2, 256, HGS_TOTAL>>>(attnh_p, wpT_p, b_proj, out, nullptr,
                                     Bc * Sc, Ec, Ec, 0);
}

// round 9
// speedup vs baseline: 2.3105x; 1.2204x over previous
#include <cuda_runtime.h>
#include <cuda_fp16.h>
#include <math.h>
#include <stdint.h>

#define Bc 4
#define Sc 2048
#define Ec 768
#define Hc 12
#define Dc 64
#define E3 2304
#define NGLOB 204

// Scratch (device globals; no runtime allocation allowed)
__device__ __half g_qkvh[(size_t)Bc * Sc * E3];
__device__ __half g_attnh[(size_t)Bc * Sc * Ec];
__device__ __half g_xh[(size_t)Bc * Sc * Ec];
__device__ __half g_waT[(size_t)E3 * Ec];
__device__ __half g_wpT[(size_t)Ec * Ec];
__device__ __half g_vTh[(size_t)Bc * Hc * Dc * Sc];
__device__ __half g_Kgh[16 * 256 * 64];
__device__ __half g_VgTh[16 * 64 * 256];
__device__ int    g_gjpad[256];
__device__ int    g_gstart[32];

// ---------------------------------------------------------------------------
__device__ __forceinline__ void mma_f16(float* d, const unsigned* a, unsigned b0, unsigned b1) {
    asm volatile(
        "mma.sync.aligned.m16n8k16.row.col.f32.f16.f16.f32 "
        "{%0,%1,%2,%3}, {%4,%5,%6,%7}, {%8,%9}, {%0,%1,%2,%3};"
        : "+f"(d[0]), "+f"(d[1]), "+f"(d[2]), "+f"(d[3])
        : "r"(a[0]), "r"(a[1]), "r"(a[2]), "r"(a[3]), "r"(b0), "r"(b1));
}
__device__ __forceinline__ void ldsm4(unsigned& r0, unsigned& r1, unsigned& r2, unsigned& r3,
                                      uint32_t addr) {
    asm volatile("ldmatrix.sync.aligned.m8n8.x4.shared.b16 {%0,%1,%2,%3}, [%4];"
                 : "=r"(r0), "=r"(r1), "=r"(r2), "=r"(r3) : "r"(addr));
}
__device__ __forceinline__ uint32_t smem_u32(const void* p) {
    uint32_t a;
    asm("{ .reg .u64 t; cvta.to.shared.u64 t, %1; cvt.u32.u64 %0, t; }" : "=r"(a) : "l"(p));
    return a;
}
__device__ __forceinline__ void cpa16(uint32_t dst, const void* src) {
    asm volatile("cp.async.cg.shared.global [%0], [%1], 16;" :: "r"(dst), "l"(src));
}
__device__ __forceinline__ void cpa_commit() {
    asm volatile("cp.async.commit_group;" ::: "memory");
}
__device__ __forceinline__ unsigned h2scale8(unsigned v) {   // *0.125 exact
    __half2 a = *(__half2*)&v;
    a = __hmul2(a, __half2half2(__ushort_as_half((unsigned short)0x3000)));
    return *(unsigned*)&a;
}
__device__ __forceinline__ unsigned packh2(float lo, float hi) {
    __half2 h = __floats2half2_rn(lo, hi);
    return *(unsigned*)&h;
}

// ---------------------------------------------------------------------------
__global__ void gpos_kernel() {
    int t = threadIdx.x;
    const float step = (float)((double)(Sc - 1) / (double)(NGLOB - 1));
    int j = -1;
    if (t < NGLOB) {
        if (t == NGLOB - 1) j = Sc - 1;
        else                j = (int)(__fmul_rn((float)t, step));
        if (j < 0) j = 0;
        if (j > Sc - 1) j = Sc - 1;
    }
    g_gjpad[t] = j;
    __syncthreads();
    if (t < 32) {
        int q0 = t * 64, cnt = 0;
        for (int k = 0; k < NGLOB; k++) cnt += (g_gjpad[k] <= q0) ? 1 : 0;
        g_gstart[t] = cnt;
    }
}

__global__ void cvth_kernel(const float* __restrict__ in, __half* __restrict__ outp, int n4) {
    int i = blockIdx.x * blockDim.x + threadIdx.x;
    if (i < n4) {
        float4 v = ((const float4*)in)[i];
        __half2 h0 = __floats2half2_rn(v.x, v.y);
        __half2 h1 = __floats2half2_rn(v.z, v.w);
        uint2 u;
        u.x = *(unsigned*)&h0;
        u.y = *(unsigned*)&h1;
        ((uint2*)outp)[i] = u;
    }
}

__global__ void cvtT_kernel(const float* __restrict__ W, __half* __restrict__ WT, int K, int N) {
    __shared__ float t[32][33];
    int n0 = blockIdx.x * 32, k0 = blockIdx.y * 32;
    int tx = threadIdx.x, ty = threadIdx.y;
#pragma unroll
    for (int i = 0; i < 4; i++)
        t[ty + i * 8][tx] = W[(size_t)(k0 + ty + i * 8) * N + n0 + tx];
    __syncthreads();
#pragma unroll
    for (int i = 0; i < 4; i++)
        WT[(size_t)(n0 + ty + i * 8) * K + k0 + tx] = __float2half(t[tx][ty + i * 8]);
}

__global__ __launch_bounds__(256) void vT_kernel(const __half* __restrict__ qkv,
                                                 __half* __restrict__ vT) {
    __shared__ __half t[64][72];
    int blk = blockIdx.x;
    int st = blk & 31, bh = blk >> 5;
    int b = bh / Hc, h = bh % Hc;
    const __half* vb = qkv + (size_t)b * Sc * E3 + 2 * Ec + h * Dc;
    int s0 = st << 6;
    int tid = threadIdx.x;
#pragma unroll
    for (int i = 0; i < 2; i++) {
        int idx = tid + i * 256;
        int row = idx >> 3, c16 = idx & 7;
        uint4 v = *(const uint4*)(vb + (size_t)(s0 + row) * E3 + c16 * 8);
        *(uint4*)&t[row][c16 * 8] = v;
    }
    __syncthreads();
    const unsigned short* ts = (const unsigned short*)&t[0][0];
#pragma unroll
    for (int i = 0; i < 2; i++) {
        int idx = tid + i * 256;
        int d = idx >> 3, seg = (idx & 7) * 8;
        uint4 u;
        unsigned short* us = (unsigned short*)&u;
#pragma unroll
        for (int j = 0; j < 8; j++) us[j] = ts[(seg + j) * 72 + d];
        *(uint4*)(vT + ((size_t)bh * Dc + d) * Sc + s0 + seg) = u;
    }
}

__global__ __launch_bounds__(256) void gather_kernel(const __half* __restrict__ qkv,
                                                     const __half* __restrict__ vT) {
    int blk = blockIdx.x;
    int b = blk >> 2, h = 8 + (blk & 3);
    const __half* kb = qkv + (size_t)b * Sc * E3 + Ec + h * Dc;
    __half* Kg = g_Kgh + (size_t)blk * 256 * 64;
    __half* VgT = g_VgTh + (size_t)blk * 64 * 256;
    int tid = threadIdx.x;
#pragma unroll
    for (int i = 0; i < 8; i++) {
        int idx = tid + i * 256;
        int slot = idx >> 3, c16 = idx & 7;
        int j = g_gjpad[slot];
        uint4 v = make_uint4(0u, 0u, 0u, 0u);
        if (j >= 0) v = *(const uint4*)(kb + (size_t)j * E3 + c16 * 8);
        *(uint4*)(Kg + (size_t)slot * 64 + c16 * 8) = v;
    }
    int j = g_gjpad[tid];
    const __half* vrow = vT + (size_t)(b * Hc + h) * Dc * Sc;
    __half z = __ushort_as_half((unsigned short)0);
#pragma unroll
    for (int d = 0; d < 64; d++) {
        __half val = (j >= 0) ? vrow[(size_t)d * Sc + j] : z;
        VgT[d * 256 + tid] = val;
    }
}

// ---------------------------------------------------------------------------
// fp16 GEMM (m16n8k16) with 3-stage cp.async pipeline + ldmatrix fragments.
// ---------------------------------------------------------------------------
#define HST_BYTES 20480
#define HST_BOFF  10240
#define HGS_TOTAL (3 * HST_BYTES)

__device__ __forceinline__ void copy_stage_h(const __half* __restrict__ A, const __half* __restrict__ WT,
                                             int m0, int n0, int K, int kt,
                                             uint32_t sbase, int tid) {
    const int kb = kt * 32;
    const uint32_t sA = sbase, sB = sbase + HST_BOFF;
#pragma unroll
    for (int i = 0; i < 2; i++) {
        int idx = tid + i * 256;
        int row = idx >> 2, ch = idx & 3;
        cpa16(sA + row * 80 + ch * 16, A + (size_t)(m0 + row) * K + kb + ch * 8);
    }
#pragma unroll
    for (int i = 0; i < 2; i++) {
        int idx = tid + i * 256;
        int row = idx >> 2, ch = idx & 3;
        cpa16(sB + row * 80 + ch * 16, WT + (size_t)(n0 + row) * K + kb + ch * 8);
    }
    cpa_commit();
}

__global__ __launch_bounds__(256, 2) void gemm_f16(
    const __half* __restrict__ A, const __half* __restrict__ WT,
    const float* __restrict__ bias, float* __restrict__ Cf, __half* __restrict__ Ch,
    int M, int N, int K, int halfOut)
{
    extern __shared__ char smem[];
    const uint32_t sb = smem_u32(smem);

    const int tid = threadIdx.x;
    const int lane = tid & 31;
    const int w = tid >> 5;
    const int g = lane >> 2, c = lane & 3;
    const int wm = (w & 3) * 32;
    const int wn = (w >> 2) * 64;
    const int m0 = blockIdx.y << 7, n0 = blockIdx.x << 7;
    const int NT = K >> 5;

    // ldmatrix per-thread addresses (relative to stage base)
    uint32_t aOff[2], bOff[4];
#pragma unroll
    for (int mt = 0; mt < 2; mt++)
        aOff[mt] = (uint32_t)(wm + mt * 16 + (lane & 15)) * 80 + ((lane >> 4) ? 16u : 0u);
#pragma unroll
    for (int p = 0; p < 4; p++)
        bOff[p] = HST_BOFF +
                  (uint32_t)(wn + 16 * p + ((lane >> 4) & 1) * 8 + (lane & 7)) * 80 +
                  ((lane >> 3) & 1) * 16;

    float acc[2][8][4];
#pragma unroll
    for (int mt = 0; mt < 2; mt++)
#pragma unroll
        for (int nt = 0; nt < 8; nt++)
#pragma unroll
            for (int i = 0; i < 4; i++) acc[mt][nt][i] = 0.f;

    copy_stage_h(A, WT, m0, n0, K, 0, sb, tid);
    copy_stage_h(A, WT, m0, n0, K, 1, sb + HST_BYTES, tid);
    copy_stage_h(A, WT, m0, n0, K, 2, sb + 2 * HST_BYTES, tid);

    for (int kt = 0; kt < NT; kt++) {
        asm volatile("cp.async.wait_group 2;" ::: "memory");
        __syncthreads();

        const uint32_t stg = sb + (kt % 3) * HST_BYTES;
#pragma unroll
        for (int ks = 0; ks < 2; ks++) {
            const uint32_t ko = ks * 32;
            unsigned a[2][4];
            ldsm4(a[0][0], a[0][1], a[0][2], a[0][3], stg + aOff[0] + ko);
            ldsm4(a[1][0], a[1][1], a[1][2], a[1][3], stg + aOff[1] + ko);
#pragma unroll
            for (int p = 0; p < 4; p++) {
                unsigned b0, b1, b2, b3;
                ldsm4(b0, b1, b2, b3, stg + bOff[p] + ko);
                mma_f16(acc[0][2 * p], a[0], b0, b1);
                mma_f16(acc[1][2 * p], a[1], b0, b1);
                mma_f16(acc[0][2 * p + 1], a[0], b2, b3);
                mma_f16(acc[1][2 * p + 1], a[1], b2, b3);
            }
        }
        __syncthreads();

        if (kt + 3 < NT) copy_stage_h(A, WT, m0, n0, K, kt + 3, sb + (kt % 3) * HST_BYTES, tid);
        else             cpa_commit();
    }

#pragma unroll
    for (int mt = 0; mt < 2; mt++) {
        int r0 = m0 + wm + mt * 16 + g;
#pragma unroll
        for (int nt = 0; nt < 8; nt++) {
            int col = n0 + wn + nt * 8 + 2 * c;
            float bv0 = bias[col], bv1 = bias[col + 1];
            float v00 = acc[mt][nt][0] + bv0, v01 = acc[mt][nt][1] + bv1;
            float v10 = acc[mt][nt][2] + bv0, v11 = acc[mt][nt][3] + bv1;
            if (halfOut) {
                *(__half2*)(Ch + (size_t)r0 * N + col) = __floats2half2_rn(v00, v01);
                *(__half2*)(Ch + (size_t)(r0 + 8) * N + col) = __floats2half2_rn(v10, v11);
            } else {
                *(float2*)(Cf + (size_t)r0 * N + col) = make_float2(v00, v01);
                *(float2*)(Cf + (size_t)(r0 + 8) * N + col) = make_float2(v10, v11);
            }
        }
    }
}

// ---------------------------------------------------------------------------
// fp16 attention, no-rescale softmax (scores bounded), mask fast-paths,
// LPT 1D grid (global heads first, qt descending), ldmatrix fragments.
// ---------------------------------------------------------------------------
#define AST_BYTES 18432
#define AST_VOFF  9216

__device__ __forceinline__ void attn_issue(
    int it, int n_causal, int n_tiles, int kt_base, int ct0,
    const __half* __restrict__ kb, const __half* __restrict__ vTb,
    const __half* __restrict__ KgB, const __half* __restrict__ VgTB,
    uint32_t sbase, int tid)
{
    if (it >= n_tiles) { cpa_commit(); return; }
    const uint32_t sK = sbase, sV = sbase + AST_VOFF;
    if (it < n_causal) {
        const int k0 = (kt_base + it) << 6;
#pragma unroll
        for (int i = 0; i < 4; i++) {
            int idx = tid + i * 128;
            int slot = idx >> 3, c16 = idx & 7;
            cpa16(sK + slot * 144 + c16 * 16, kb + (size_t)(k0 + slot) * E3 + c16 * 8);
            cpa16(sV + slot * 144 + c16 * 16, vTb + (size_t)slot * Sc + k0 + c16 * 8);
        }
    } else {
        const int ct = ct0 + it - n_causal;
        const __half* Kt = KgB + (size_t)ct * 64 * 64;
#pragma unroll
        for (int i = 0; i < 4; i++) {
            int idx = tid + i * 128;
            int slot = idx >> 3, c16 = idx & 7;
            cpa16(sK + slot * 144 + c16 * 16, Kt + (size_t)slot * 64 + c16 * 8);
            cpa16(sV + slot * 144 + c16 * 16, VgTB + (size_t)slot * 256 + ct * 64 + c16 * 8);
        }
    }
    cpa_commit();
}

__global__ __launch_bounds__(128) void attn_tc(
    const __half* __restrict__ qkv, __half* __restrict__ out, int half_w)
{
    extern __shared__ char smem[];
    const uint32_t sb = smem_u32(smem);

    // LPT mapping: 512 global-head blocks first (qt descending), then local.
    const int bid = blockIdx.x;
    int b, h, qt;
    if (bid < 512) {
        h = 8 + (bid & 3);
        qt = 31 - ((bid >> 2) & 31);
        b = bid >> 7;
    } else {
        int l = bid - 512;
        h = l & 7;
        qt = 31 - ((l >> 3) & 31);
        b = l >> 8;
    }
    const bool is_local = (h < 8);
    const int q0 = qt << 6;
    const int tid = threadIdx.x;
    const int lane = tid & 31;
    const int w = tid >> 5;
    const int g = lane >> 2, c = lane & 3;

    const __half* qb = qkv + (size_t)b * Sc * E3 + h * Dc;
    const __half* kb = qb + Ec;
    const __half* vTb = g_vTh + (size_t)(b * Hc + h) * Dc * Sc;
    const __half* KgB = g_Kgh + (size_t)(b * 4 + (h - 8)) * 256 * 64;
    const __half* VgTB = g_VgTh + (size_t)(b * 4 + (h - 8)) * 64 * 256;

    const int r0 = q0 + 16 * w + g;
    const int r1 = r0 + 8;

    // ldmatrix addresses for K and V^T fragments
    uint32_t kOff[4], vOff[4];
#pragma unroll
    for (int p = 0; p < 4; p++) {
        uint32_t row = 16 * p + ((lane >> 4) & 1) * 8 + (lane & 7);
        uint32_t co = ((lane >> 3) & 1) * 16;
        kOff[p] = row * 144 + co;
        vOff[p] = AST_VOFF + row * 144 + co;
    }

    // Q fragments (scaled 1/8)
    const unsigned* qw0 = (const unsigned*)(qb + (size_t)r0 * E3);
    const unsigned* qw1 = (const unsigned*)(qb + (size_t)r1 * E3);
    unsigned qa[4][4];
#pragma unroll
    for (int ks = 0; ks < 4; ks++) {
        qa[ks][0] = h2scale8(qw0[8 * ks + c]);
        qa[ks][1] = h2scale8(qw1[8 * ks + c]);
        qa[ks][2] = h2scale8(qw0[8 * ks + 4 + c]);
        qa[ks][3] = h2scale8(qw1[8 * ks + 4 + c]);
    }

    float o[8][4];
#pragma unroll
    for (int nt = 0; nt < 8; nt++)
#pragma unroll
        for (int i = 0; i < 4; i++) o[nt][i] = 0.f;
    float l0 = 0.f, l1 = 0.f;   // per-lane partial row sums

    int kt_base, n_causal, n_tiles, ct0 = 0;
    if (is_local) {
        int lo = (q0 - half_w) >> 6;
        kt_base = lo > 0 ? lo : 0;
        n_causal = qt - kt_base + 1;
        n_tiles = n_causal;
    } else {
        kt_base = 0;
        n_causal = qt + 1;
        ct0 = g_gstart[qt] >> 6;
        n_tiles = n_causal + (4 - ct0);
    }

    attn_issue(0, n_causal, n_tiles, kt_base, ct0, kb, vTb, KgB, VgTB, sb, tid);
    attn_issue(1, n_causal, n_tiles, kt_base, ct0, kb, vTb, KgB, VgTB, sb + AST_BYTES, tid);

    for (int it = 0; it < n_tiles; it++) {
        asm volatile("cp.async.wait_group 1;" ::: "memory");
        __syncthreads();

        const uint32_t stg = sb + (it & 1) * AST_BYTES;
        const bool compact = (!is_local) && (it >= n_causal);
        const int kt = kt_base + it;
        const int k0 = kt << 6;
        const int ctb = compact ? (ct0 + it - n_causal) * 64 : 0;

        // QK^T
        float s[8][4];
#pragma unroll
        for (int nt = 0; nt < 8; nt++)
#pragma unroll
            for (int i = 0; i < 4; i++) s[nt][i] = 0.f;
#pragma unroll
        for (int ks = 0; ks < 4; ks++) {
            const uint32_t ko = ks * 32;
#pragma unroll
            for (int p = 0; p < 4; p++) {
                unsigned k0f, k1f, k2f, k3f;
                ldsm4(k0f, k1f, k2f, k3f, stg + kOff[p] + ko);
                mma_f16(s[2 * p], qa[ks], k0f, k1f);
                mma_f16(s[2 * p + 1], qa[ks], k2f, k3f);
            }
        }

        // mask fast-paths: 0=none, 1=diag causal, 2=window lower, 3=compact
        int mode = compact ? 3
                 : (kt == qt ? 1
                 : ((is_local && k0 < q0 + 64 - half_w) ? 2 : 0));
        if (mode == 1) {
#pragma unroll
            for (int nt = 0; nt < 8; nt++) {
                int jA = k0 + 8 * nt + 2 * c, jB = jA + 1;
                s[nt][0] = (jA <= r0) ? s[nt][0] : -1e9f;
                s[nt][1] = (jB <= r0) ? s[nt][1] : -1e9f;
                s[nt][2] = (jA <= r1) ? s[nt][2] : -1e9f;
                s[nt][3] = (jB <= r1) ? s[nt][3] : -1e9f;
            }
        } else if (mode == 2) {
#pragma unroll
            for (int nt = 0; nt < 8; nt++) {
                int jA = k0 + 8 * nt + 2 * c, jB = jA + 1;
                s[nt][0] = (jA >= r0 - half_w) ? s[nt][0] : -1e9f;
                s[nt][1] = (jB >= r0 - half_w) ? s[nt][1] : -1e9f;
                s[nt][2] = (jA >= r1 - half_w) ? s[nt][2] : -1e9f;
                s[nt][3] = (jB >= r1 - half_w) ? s[nt][3] : -1e9f;
            }
        } else if (mode == 3) {
#pragma unroll
            for (int nt = 0; nt < 8; nt++) {
                int jA = g_gjpad[ctb + 8 * nt + 2 * c];
                int jB = g_gjpad[ctb + 8 * nt + 2 * c + 1];
                s[nt][0] = (jA > r0) ? s[nt][0] : -1e9f;
                s[nt][1] = (jB > r0) ? s[nt][1] : -1e9f;
                s[nt][2] = (jA > r1) ? s[nt][2] : -1e9f;
                s[nt][3] = (jB > r1) ? s[nt][3] : -1e9f;
            }
        }

        // exp (no max subtraction: |scores| <~ 2) + per-lane l partials
#pragma unroll
        for (int nt = 0; nt < 8; nt++) {
            s[nt][0] = __expf(s[nt][0]);
            s[nt][1] = __expf(s[nt][1]);
            s[nt][2] = __expf(s[nt][2]);
            s[nt][3] = __expf(s[nt][3]);
            l0 += s[nt][0] + s[nt][1];
            l1 += s[nt][2] + s[nt][3];
        }

        // PV
#pragma unroll
        for (int t2 = 0; t2 < 4; t2++) {
            unsigned pa[4];
            pa[0] = packh2(s[2 * t2][0], s[2 * t2][1]);
            pa[1] = packh2(s[2 * t2][2], s[2 * t2][3]);
            pa[2] = packh2(s[2 * t2 + 1][0], s[2 * t2 + 1][1]);
            pa[3] = packh2(s[2 * t2 + 1][2], s[2 * t2 + 1][3]);
            const uint32_t ko = t2 * 32;
#pragma unroll
            for (int p = 0; p < 4; p++) {
                unsigned v0, v1, v2, v3;
                ldsm4(v0, v1, v2, v3, stg + vOff[p] + ko);
                mma_f16(o[2 * p], pa, v0, v1);
                mma_f16(o[2 * p + 1], pa, v2, v3);
            }
        }
        __syncthreads();

        attn_issue(it + 2, n_causal, n_tiles, kt_base, ct0, kb, vTb, KgB, VgTB,
                   sb + (it & 1) * AST_BYTES, tid);
    }

    // reduce row sums across the 4 c-lanes (once, after the loop)
    l0 += __shfl_xor_sync(0xffffffffu, l0, 1);
    l0 += __shfl_xor_sync(0xffffffffu, l0, 2);
    l1 += __shfl_xor_sync(0xffffffffu, l1, 1);
    l1 += __shfl_xor_sync(0xffffffffu, l1, 2);

    float inv0 = 1.0f / l0, inv1 = 1.0f / l1;
    __half* ob0 = out + (size_t)(b * Sc + r0) * Ec + h * Dc;
    __half* ob1 = out + (size_t)(b * Sc + r1) * Ec + h * Dc;
#pragma unroll
    for (int nt = 0; nt < 8; nt++) {
        int d = 8 * nt + 2 * c;
        *(__half2*)(ob0 + d) = __floats2half2_rn(o[nt][0] * inv0, o[nt][1] * inv0);
        *(__half2*)(ob1 + d) = __floats2half2_rn(o[nt][2] * inv1, o[nt][3] * inv1);
    }
}

// ---------------------------------------------------------------------------
extern "C" void kernel_launch(void* const* d_in, const int* in_sizes, int n_in,
                              void* d_out, int out_size) {
    const float* x      = (const float*)d_in[0];
    const float* w_attn = (const float*)d_in[1];
    const float* b_attn = (const float*)d_in[2];
    const float* w_proj = (const float*)d_in[3];
    const float* b_proj = (const float*)d_in[4];
    float* out = (float*)d_out;

    __half *qkvh_p, *attnh_p, *xh_p, *waT_p, *wpT_p, *vT_p;
    cudaGetSymbolAddress((void**)&qkvh_p, g_qkvh);
    cudaGetSymbolAddress((void**)&attnh_p, g_attnh);
    cudaGetSymbolAddress((void**)&xh_p, g_xh);
    cudaGetSymbolAddress((void**)&waT_p, g_waT);
    cudaGetSymbolAddress((void**)&wpT_p, g_wpT);
    cudaGetSymbolAddress((void**)&vT_p, g_vTh);

    int wdw = (int)(128.0 * sqrt((double)Sc / 128.0));
    if (wdw < 32) wdw = 32;
    if (wdw > 512) wdw = 512;
    int half_w = wdw / 2;

    cudaFuncSetAttribute(gemm_f16, cudaFuncAttributeMaxDynamicSharedMemorySize, HGS_TOTAL);
    cudaFuncSetAttribute(attn_tc, cudaFuncAttributeMaxDynamicSharedMemorySize, 2 * AST_BYTES);

    gpos_kernel<<<1, 256>>>();
    {
        int n4 = (Bc * Sc * Ec) / 4;
        cvth_kernel<<<(n4 + 255) / 256, 256>>>(x, xh_p, n4);
    }
    {
        dim3 gt(E3 / 32, Ec / 32);
        cvtT_kernel<<<gt, dim3(32, 8)>>>(w_attn, waT_p, Ec, E3);
    }
    {
        dim3 gt(Ec / 32, Ec / 32);
        cvtT_kernel<<<gt, dim3(32, 8)>>>(w_proj, wpT_p, Ec, Ec);
    }

    dim3 g1(E3 / 128, (Bc * Sc) / 128);
    gemm_f16<<<g1, 256, HGS_TOTAL>>>(xh_p, waT_p, b_attn, nullptr, qkvh_p,
                                     Bc * Sc, E3, Ec, 1);

    vT_kernel<<<Bc * Hc * 32, 256>>>(qkvh_p, vT_p);
    gather_kernel<<<16, 256>>>(qkvh_p, vT_p);

    attn_tc<<<1536, 128, 2 * AST_BYTES>>>(qkvh_p, attnh_p, half_w);

    dim3 g2(Ec / 128, (Bc * Sc) / 128);
    gemm_f16<<<g2, 256, HGS_TOTAL>>>(attnh_p, wpT_p, b_proj, out, nullptr,
                                     Bc * Sc, Ec, Ec, 0);
}